// round 13
// baseline (speedup 1.0000x reference)
#include <cuda_runtime.h>
#include <math.h>

#define D 70
#define NMAX 50000
#define EMAX 800000
#define GG 128

// ---------------- device scratch ----------------
__device__ float g_h[NMAX * D];
__device__ float g_A[NMAX * D];
__device__ float g_B[NMAX * D];
__device__ float g_Dh[NMAX * D];
__device__ float g_Eh[NMAX * D];
__device__ float g_hraw[NMAX * D];
__device__ float g_S[EMAX * D];
__device__ float g_enew[EMAX * D];
__device__ float g_ce[EMAX * D];
__device__ float g_statsf[4][64][D];
__device__ float g_norm[4 * D];
__device__ float g_hg[GG * D];
__device__ float g_cnt[GG];
__device__ float g_u[D];
__device__ float g_v[D];
__device__ int g_cnt_n[NMAX];
__device__ int g_rowoff[NMAX + 1];
__device__ int g_psrc[EMAX];
__device__ float g_pef[EMAX];
__device__ float g_psn[EMAX];

// ---------------- packed fp32x2 helpers (sm_100+) ----------------
__device__ __forceinline__ unsigned long long pk2(float lo, float hi) {
    unsigned long long r;
    asm("mov.b64 %0, {%1, %2};" : "=l"(r) : "f"(lo), "f"(hi));
    return r;
}
__device__ __forceinline__ void ffma2(unsigned long long& d, unsigned long long a,
                                      unsigned long long b) {
    asm("fma.rn.f32x2 %0, %1, %2, %0;" : "+l"(d) : "l"(a), "l"(b));
}

// ---------------- sort: histogram / scan / scatter ----------------
__global__ void hist_kernel(const int* __restrict__ dst, int E_) {
    int i = blockIdx.x * blockDim.x + threadIdx.x;
    if (i < E_) atomicAdd(&g_cnt_n[dst[i]], 1);
}

__global__ void scan_kernel(int Nn, int E_) {
    __shared__ int s[1024];
    int t = threadIdx.x;
    int chunk = (Nn + 1023) / 1024;
    int begin = t * chunk, end = min(begin + chunk, Nn);
    int sum = 0;
    for (int i = begin; i < end; i++) sum += g_cnt_n[i];
    s[t] = sum;
    __syncthreads();
    for (int off = 1; off < 1024; off <<= 1) {
        int tmp = (t >= off) ? s[t - off] : 0;
        __syncthreads();
        s[t] += tmp;
        __syncthreads();
    }
    int acc = s[t] - sum;
    for (int i = begin; i < end; i++) {
        int c = g_cnt_n[i];
        g_rowoff[i] = acc;
        acc += c;
        g_cnt_n[i] = 0;
    }
    if (t == 0) g_rowoff[Nn] = E_;
}

__global__ void scatter_sort_kernel(const int* __restrict__ src, const int* __restrict__ dst,
                                    const float* __restrict__ ef, const float* __restrict__ sn,
                                    int E_) {
    int i = blockIdx.x * blockDim.x + threadIdx.x;
    if (i < E_) {
        int d = dst[i];
        int pos = g_rowoff[d] + atomicAdd(&g_cnt_n[d], 1);
        g_psrc[pos] = src[i];
        g_pef[pos] = ef[i];
        g_psn[pos] = sn[i];
    }
}

// ---------------- layer-0 rank-1 Ce precompute ----------------
__global__ void uv_kernel(const float* __restrict__ WembE, const float* __restrict__ bembE,
                          const float* __restrict__ WC, const float* __restrict__ bC) {
    int j = threadIdx.x;
    if (j >= D) return;
    float u = 0.f, v = 0.f;
    for (int k = 0; k < D; k++) {
        float w = WC[k * D + j];
        u += WembE[k] * w;
        v += bembE[k] * w;
    }
    g_u[j] = u;
    g_v[j] = v + bC[j];
}

// ---------------- embedding GEMM [N,146]@[146,70] ----------------
template <int K>
__global__ void gemm70_kernel(const float* __restrict__ X, const float* __restrict__ W,
                              const float* __restrict__ bias, float* __restrict__ Y, int M) {
    extern __shared__ float smem[];
    float* sW = smem;
    float* sX = smem + K * D;
    __shared__ float sb[D];
    const int tx = threadIdx.x, ty = threadIdx.y;
    const int tid = ty * 14 + tx;
    for (int i = tid; i < K * D; i += 224) sW[i] = W[i];
    if (tid < D) sb[tid] = bias[tid];
    __syncthreads();

    const int base = blockIdx.x * 64;
    const int cnt = min(64, M - base);
    for (int i = tid; i < cnt * K; i += 224) sX[i] = X[(size_t)base * K + i];
    __syncthreads();

    const int c0 = tx * 5, r0 = ty * 4;
    float acc[4][5];
#pragma unroll
    for (int r = 0; r < 4; r++)
#pragma unroll
        for (int c = 0; c < 5; c++) acc[r][c] = sb[c0 + c];

#pragma unroll 2
    for (int k = 0; k < K; k++) {
        float w0 = sW[k * D + c0 + 0], w1 = sW[k * D + c0 + 1], w2 = sW[k * D + c0 + 2];
        float w3 = sW[k * D + c0 + 3], w4 = sW[k * D + c0 + 4];
#pragma unroll
        for (int r = 0; r < 4; r++) {
            float xv = (r0 + r < cnt) ? sX[(r0 + r) * K + k] : 0.f;
            acc[r][0] += xv * w0; acc[r][1] += xv * w1; acc[r][2] += xv * w2;
            acc[r][3] += xv * w3; acc[r][4] += xv * w4;
        }
    }
#pragma unroll
    for (int r = 0; r < 4; r++) {
        int row = base + r0 + r;
        if (row < M) {
#pragma unroll
            for (int c = 0; c < 5; c++) Y[(size_t)row * D + c0 + c] = acc[r][c];
        }
    }
}

// ---------------- fused node kernel: optional h-update + 4 GEMMs (f32x2) ----------------
__global__ __launch_bounds__(224, 3) void gemm4_kernel(
    const float* __restrict__ WA, const float* __restrict__ bA,
    const float* __restrict__ WB, const float* __restrict__ bB,
    const float* __restrict__ WD, const float* __restrict__ bD,
    const float* __restrict__ WE, const float* __restrict__ bE,
    const float* __restrict__ hgam, const float* __restrict__ hbet,
    int fuse, int Nn) {
    extern __shared__ __align__(16) float dsm[];
    float* sW = dsm;              // 70*70
    float* sX = dsm + D * D;      // 128*70
    __shared__ float sb[D];
    __shared__ float sMu[D], sRs[D], sGa[D], sBe[D];
    const int tx = threadIdx.x, ty = threadIdx.y;
    const int tid = ty * 7 + tx;
    if (fuse && tid < D) {
        sMu[tid] = g_norm[tid];
        sRs[tid] = g_norm[D + tid];
        sGa[tid] = hgam[tid];
        sBe[tid] = hbet[tid];
    }
    const int base = blockIdx.x * 128;
    const int cnt = min(128, Nn - base);
    __syncthreads();
    for (int idx = tid; idx < cnt * D; idx += 224) {
        size_t gi = (size_t)base * D + idx;
        float v = g_h[gi];
        if (fuse) {
            int r = idx / D;
            int c = idx - r * D;
            float hr = g_hraw[gi];
            v += fmaxf((hr - sMu[c]) * sRs[c] * sGa[c] + sBe[c], 0.f);
            g_h[gi] = v;
        }
        sX[idx] = v;
    }
    if (cnt < 128)
        for (int idx = cnt * D + tid; idx < 128 * D; idx += 224) sX[idx] = 0.f;

    const float* Ws[4] = {WA, WB, WD, WE};
    const float* bs[4] = {bA, bB, bD, bE};
    float* outs[4] = {g_A, g_B, g_Dh, g_Eh};

    const int c0 = tx * 10;
    for (int m = 0; m < 4; m++) {
        __syncthreads();
        for (int i = tid; i < D * D; i += 224) sW[i] = Ws[m][i];
        if (tid < D) sb[tid] = bs[m][tid];
        __syncthreads();

        unsigned long long acc[4][5];
#pragma unroll
        for (int c = 0; c < 5; c++) {
            unsigned long long bp = pk2(sb[c0 + 2 * c], sb[c0 + 2 * c + 1]);
#pragma unroll
            for (int r = 0; r < 4; r++) acc[r][c] = bp;
        }

#pragma unroll 2
        for (int k = 0; k < D; k++) {
            unsigned long long w[5];
#pragma unroll
            for (int c = 0; c < 5; c++)
                w[c] = *(const unsigned long long*)&sW[k * D + c0 + 2 * c];
#pragma unroll
            for (int r = 0; r < 4; r++) {
                float xv = sX[(ty + 32 * r) * D + k];
                unsigned long long xp = pk2(xv, xv);
#pragma unroll
                for (int c = 0; c < 5; c++) ffma2(acc[r][c], xp, w[c]);
            }
        }
        float* out = outs[m];
#pragma unroll
        for (int r = 0; r < 4; r++) {
            int row = base + ty + 32 * r;
            if (row < Nn) {
#pragma unroll
                for (int c = 0; c < 5; c++)
                    *(unsigned long long*)&out[(size_t)row * D + c0 + 2 * c] = acc[r][c];
            }
        }
    }
}

// ---------------- streaming edge GEMM (f32x2) over edge range [eBase, E_) ----------------
template <int FIRST, int WRITE_S>
__global__ __launch_bounds__(224, 3) void edgegemm_kernel(
    const float* __restrict__ WC,
    const float* __restrict__ egam, const float* __restrict__ ebet,
    int eBase, int E_) {
    extern __shared__ __align__(16) float dsm[];
    float* sW = dsm;             // 70*70
    float* sX = dsm + D * D;     // 128*70
    __shared__ float sef[128];
    __shared__ float su[D], sv[D], sMu[D], sRs[D], sGa[D], sBe[D];
    const int tx = threadIdx.x, ty = threadIdx.y;
    const int tid = ty * 7 + tx;
    for (int i = tid; i < D * D; i += 224) sW[i] = WC[i];
    if (tid < D) {
        su[tid] = g_u[tid];
        sv[tid] = g_v[tid];
        sMu[tid] = g_norm[2 * D + tid];
        sRs[tid] = g_norm[3 * D + tid];
        sGa[tid] = egam[tid];
        sBe[tid] = ebet[tid];
    }
    __syncthreads();

    const int base = eBase + blockIdx.x * 128;
    const int cnt = min(128, E_ - base);
    for (int idx = tid; idx < cnt * D; idx += 224) {
        size_t gi = (size_t)base * D + idx;
        int r = idx / D;
        int c = idx - r * D;
        float R = fmaxf((g_enew[gi] - sMu[c]) * sRs[c] * sGa[c] + sBe[c], 0.f);
        float Sv = FIRST ? R : (g_S[gi] + R);
        sX[idx] = Sv;
        if (WRITE_S) g_S[gi] = Sv;
    }
    if (cnt < 128)
        for (int idx = cnt * D + tid; idx < 128 * D; idx += 224) sX[idx] = 0.f;
    for (int i = tid; i < 128; i += 224) sef[i] = (i < cnt) ? g_pef[base + i] : 0.f;
    __syncthreads();

    const int c0 = tx * 10;
    unsigned long long acc[4][5];
#pragma unroll
    for (int r = 0; r < 4; r++) {
        float efv = sef[ty + 32 * r];
#pragma unroll
        for (int c = 0; c < 5; c++)
            acc[r][c] = pk2(sv[c0 + 2 * c] + efv * su[c0 + 2 * c],
                            sv[c0 + 2 * c + 1] + efv * su[c0 + 2 * c + 1]);
    }

#pragma unroll 2
    for (int k = 0; k < D; k++) {
        unsigned long long w[5];
#pragma unroll
        for (int c = 0; c < 5; c++)
            w[c] = *(const unsigned long long*)&sW[k * D + c0 + 2 * c];
#pragma unroll
        for (int r = 0; r < 4; r++) {
            float xv = sX[(ty + 32 * r) * D + k];
            unsigned long long xp = pk2(xv, xv);
#pragma unroll
            for (int c = 0; c < 5; c++) ffma2(acc[r][c], xp, w[c]);
        }
    }
#pragma unroll
    for (int r = 0; r < 4; r++) {
        int ei = base + ty + 32 * r;
        if (ei < E_) {
#pragma unroll
            for (int c = 0; c < 5; c++)
                *(unsigned long long*)&g_ce[(size_t)ei * D + c0 + 2 * c] = acc[r][c];
        }
    }
}

// ---------------- node aggregation: warp-per-node, 3 cols/lane ----------------
// CHUNK: 0=all nodes, 1=nodes whose edge range ends <= Esplit, 2=rest.
template <int RANK1, int LAST, int CHUNK>
__global__ __launch_bounds__(256) void agg_kernel(const float* __restrict__ snorm_n,
                                                  int Nn, int Esplit) {
    const int lane = threadIdx.x & 31;
    const int w = threadIdx.x >> 5;
    const int n = blockIdx.x * 8 + w;

    if (CHUNK != 2) {  // reset scatter cursors once per layer
        int i = blockIdx.x * 256 + threadIdx.x;
        if (i < Nn) g_cnt_n[i] = 0;
    }

    __shared__ float sStat[4][D];
    for (int i = threadIdx.x; i < 4 * D; i += 256) ((float*)sStat)[i] = 0.f;
    __syncthreads();

    const int j0 = lane, j1 = lane + 32;
    const bool m2 = lane < (D - 64);
    const int j2 = m2 ? lane + 64 : lane;

    bool active = false;
    float hv0 = 0.f, hv1 = 0.f, hv2 = 0.f;
    float lsE0 = 0, lqE0 = 0, lsE1 = 0, lqE1 = 0, lsE2 = 0, lqE2 = 0;

    if (n < Nn) {
        const int e0 = g_rowoff[n], e1 = g_rowoff[n + 1];
        if (CHUNK == 0 || (CHUNK == 1 && e1 <= Esplit) || (CHUNK == 2 && e1 > Esplit)) {
            active = true;
            float u0, v0, u1, v1, u2, v2;
            if (RANK1) {
                u0 = g_u[j0]; v0 = g_v[j0];
                u1 = g_u[j1]; v1 = g_v[j1];
                u2 = g_u[j2]; v2 = g_v[j2];
            }
            const size_t nb = (size_t)n * D;
            const float eh0 = g_Eh[nb + j0], eh1 = g_Eh[nb + j1], eh2 = g_Eh[nb + j2];
            float num0 = 0, den0 = 0, num1 = 0, den1 = 0, num2 = 0, den2 = 0;
            for (int e = e0; e < e1; e++) {
                int s = g_psrc[e];
                size_t sb = (size_t)s * D;
                size_t eb = (size_t)e * D;
                float ce0, ce1, ce2;
                if (RANK1) {
                    float ef = g_pef[e];
                    ce0 = ef * u0 + v0; ce1 = ef * u1 + v1; ce2 = ef * u2 + v2;
                } else {
                    ce0 = g_ce[eb + j0]; ce1 = g_ce[eb + j1]; ce2 = g_ce[eb + j2];
                }
                float dh0 = g_Dh[sb + j0], dh1 = g_Dh[sb + j1], dh2 = g_Dh[sb + j2];
                float bb0 = g_B[sb + j0], bb1 = g_B[sb + j1], bb2 = g_B[sb + j2];
                float en0 = ce0 + dh0 + eh0;
                float en1 = ce1 + dh1 + eh1;
                float en2 = ce2 + dh2 + eh2;
                float sg0 = 1.f / (1.f + __expf(-en0));
                float sg1 = 1.f / (1.f + __expf(-en1));
                float sg2 = 1.f / (1.f + __expf(-en2));
                num0 += bb0 * sg0; den0 += sg0;
                num1 += bb1 * sg1; den1 += sg1;
                num2 += bb2 * sg2; den2 += sg2;
                if (!LAST) {
                    float sn = g_psn[e];
                    float s0 = en0 * sn, s1 = en1 * sn, s2 = en2 * sn;
                    g_enew[eb + j0] = s0;
                    g_enew[eb + j1] = s1;
                    if (m2) g_enew[eb + j2] = s2;
                    lsE0 += s0; lqE0 += s0 * s0;
                    lsE1 += s1; lqE1 += s1 * s1;
                    lsE2 += s2; lqE2 += s2 * s2;
                }
            }
            float snn = snorm_n[n];
            hv0 = (g_A[nb + j0] + num0 / (den0 + 1e-6f)) * snn;
            hv1 = (g_A[nb + j1] + num1 / (den1 + 1e-6f)) * snn;
            hv2 = (g_A[nb + j2] + num2 / (den2 + 1e-6f)) * snn;
            g_hraw[nb + j0] = hv0;
            g_hraw[nb + j1] = hv1;
            if (m2) g_hraw[nb + j2] = hv2;
        }
    }

    if (active) {
        atomicAdd(&sStat[0][j0], hv0); atomicAdd(&sStat[1][j0], hv0 * hv0);
        atomicAdd(&sStat[0][j1], hv1); atomicAdd(&sStat[1][j1], hv1 * hv1);
        if (m2) { atomicAdd(&sStat[0][j2], hv2); atomicAdd(&sStat[1][j2], hv2 * hv2); }
        if (!LAST) {
            atomicAdd(&sStat[2][j0], lsE0); atomicAdd(&sStat[3][j0], lqE0);
            atomicAdd(&sStat[2][j1], lsE1); atomicAdd(&sStat[3][j1], lqE1);
            if (m2) { atomicAdd(&sStat[2][j2], lsE2); atomicAdd(&sStat[3][j2], lqE2); }
        }
    }
    __syncthreads();
    const int slot = blockIdx.x & 63;
    const int lim = LAST ? 2 * D : 4 * D;
    for (int i = threadIdx.x; i < lim; i += 256) {
        int st = i / D, j = i - st * D;
        float val = sStat[st][j];
        if (val != 0.f) atomicAdd(&g_statsf[st][slot][j], val);
    }
}

// ---------------- finalize: reduce stat shards -> norms; next layer's u,v ----------------
__global__ void finalize_kernel(const float* __restrict__ WembE, const float* __restrict__ bembE,
                                const float* __restrict__ WCn, const float* __restrict__ bCn,
                                int Nn, int E_, int haveE) {
    int t = threadIdx.x;
    if (t < D) {
        float sh = 0.f, sq = 0.f;
        for (int s = 0; s < 64; s++) {
            sh += g_statsf[0][s][t]; g_statsf[0][s][t] = 0.f;
            sq += g_statsf[1][s][t]; g_statsf[1][s][t] = 0.f;
        }
        float mu = sh / Nn;
        float var = sq / Nn - mu * mu;
        g_norm[t] = mu;
        g_norm[D + t] = rsqrtf(fmaxf(var, 0.f) + 1e-5f);
        if (WCn) {
            float u = 0.f, v = 0.f;
            for (int k = 0; k < D; k++) {
                float w = WCn[k * D + t];
                u += WembE[k] * w;
                v += bembE[k] * w;
            }
            g_u[t] = u;
            g_v[t] = v + bCn[t];
        }
    } else if (t < 2 * D && haveE) {
        int j = t - D;
        float se = 0.f, sq = 0.f;
        for (int s = 0; s < 64; s++) {
            se += g_statsf[2][s][j]; g_statsf[2][s][j] = 0.f;
            sq += g_statsf[3][s][j]; g_statsf[3][s][j] = 0.f;
        }
        float mu = se / E_;
        float var = sq / E_ - mu * mu;
        g_norm[2 * D + j] = mu;
        g_norm[3 * D + j] = rsqrtf(fmaxf(var, 0.f) + 1e-5f);
    }
}

// ---------------- readout ----------------
__global__ void zero_readout_kernel() {
    int i = blockIdx.x * blockDim.x + threadIdx.x;
    if (i < GG * D) g_hg[i] = 0.f;
    if (i < GG) g_cnt[i] = 0.f;
}

__global__ void scatter_kernel(const int* __restrict__ gid,
                               const float* __restrict__ hgam, const float* __restrict__ hbet,
                               int Nn) {
    int j = threadIdx.x;
    float mu = g_norm[j], rs = g_norm[D + j], ga = hgam[j], bb = hbet[j];
    for (int row = blockIdx.x * 8 + threadIdx.y; row < Nn; row += gridDim.x * 8) {
        size_t idx = (size_t)row * D + j;
        float v = g_h[idx] + fmaxf((g_hraw[idx] - mu) * rs * ga + bb, 0.f);
        int g = gid[row];
        atomicAdd(&g_hg[g * D + j], v);
        if (j == 0) atomicAdd(&g_cnt[g], 1.f);
    }
}

__global__ void mlp_kernel(const float* __restrict__ W0, const float* __restrict__ b0,
                           const float* __restrict__ W1, const float* __restrict__ b1,
                           const float* __restrict__ W2, const float* __restrict__ b2,
                           float* __restrict__ out) {
    int g = threadIdx.x;
    if (g >= GG) return;
    float cnt = fmaxf(g_cnt[g], 1.f);
    float x[D];
#pragma unroll
    for (int k = 0; k < D; k++) x[k] = g_hg[g * D + k] / cnt;
    float y0[35];
#pragma unroll
    for (int o = 0; o < 35; o++) {
        float s = b0[o];
#pragma unroll
        for (int k = 0; k < D; k++) s += x[k] * W0[k * 35 + o];
        y0[o] = fmaxf(s, 0.f);
    }
    float y1[17];
#pragma unroll
    for (int o = 0; o < 17; o++) {
        float s = b1[o];
#pragma unroll
        for (int k = 0; k < 35; k++) s += y0[k] * W1[k * 17 + o];
        y1[o] = fmaxf(s, 0.f);
    }
#pragma unroll
    for (int o = 0; o < 10; o++) {
        float s = b2[o];
#pragma unroll
        for (int k = 0; k < 17; k++) s += y1[k] * W2[k * 10 + o];
        out[g * 10 + o] = s;
    }
}

// ---------------- host ----------------
extern "C" void kernel_launch(void* const* d_in, const int* in_sizes, int n_in,
                              void* d_out, int out_size) {
    const float* nodes   = (const float*)d_in[0];
    const float* ef      = (const float*)d_in[1];
    const float* snorm_n = (const float*)d_in[2];
    const float* snorm_e = (const float*)d_in[3];
    const int N = in_sizes[2];
    const int E_ = in_sizes[3];

    const int *src, *dst, *gid;
    const float *Wemb_h, *bemb_h, *Wemb_e, *bemb_e;
    const float *WA, *bA, *WB, *bB, *WC, *bC, *WDl, *bDl, *WEl, *bEl;
    const float *gh, *bh, *ge, *be, *W0, *b0, *W1, *b1, *W2, *b2;

    if (in_sizes[4] == E_) {
        src = (const int*)d_in[4]; dst = (const int*)d_in[5]; gid = (const int*)d_in[6];
        Wemb_h = (const float*)d_in[7];  bemb_h = (const float*)d_in[8];
        Wemb_e = (const float*)d_in[9];  bemb_e = (const float*)d_in[10];
        WA = (const float*)d_in[11]; bA = (const float*)d_in[12];
        WB = (const float*)d_in[13]; bB = (const float*)d_in[14];
        WC = (const float*)d_in[15]; bC = (const float*)d_in[16];
        WDl = (const float*)d_in[17]; bDl = (const float*)d_in[18];
        WEl = (const float*)d_in[19]; bEl = (const float*)d_in[20];
        gh = (const float*)d_in[21]; bh = (const float*)d_in[22];
        ge = (const float*)d_in[23]; be = (const float*)d_in[24];
        W0 = (const float*)d_in[25]; b0 = (const float*)d_in[26];
        W1 = (const float*)d_in[27]; b1 = (const float*)d_in[28];
        W2 = (const float*)d_in[29]; b2 = (const float*)d_in[30];
    } else {
        Wemb_h = (const float*)d_in[4];  bemb_h = (const float*)d_in[5];
        Wemb_e = (const float*)d_in[6];  bemb_e = (const float*)d_in[7];
        WA = (const float*)d_in[8];  bA = (const float*)d_in[9];
        WB = (const float*)d_in[10]; bB = (const float*)d_in[11];
        WC = (const float*)d_in[12]; bC = (const float*)d_in[13];
        WDl = (const float*)d_in[14]; bDl = (const float*)d_in[15];
        WEl = (const float*)d_in[16]; bEl = (const float*)d_in[17];
        gh = (const float*)d_in[18]; bh = (const float*)d_in[19];
        ge = (const float*)d_in[20]; be = (const float*)d_in[21];
        W0 = (const float*)d_in[22]; b0 = (const float*)d_in[23];
        W1 = (const float*)d_in[24]; b1 = (const float*)d_in[25];
        W2 = (const float*)d_in[26]; b2 = (const float*)d_in[27];
        src = (const int*)d_in[28]; dst = (const int*)d_in[29]; gid = (const int*)d_in[30];
    }
    float* out = (float*)d_out;

    float* ph;
    cudaGetSymbolAddress((void**)&ph, g_h);

    static cudaStream_t sA = nullptr, sB = nullptr;
    static cudaEvent_t evF = nullptr, evA = nullptr, evB1 = nullptr, evB2 = nullptr;
    if (sA == nullptr) {
        cudaStreamCreateWithFlags(&sA, cudaStreamNonBlocking);
        cudaStreamCreateWithFlags(&sB, cudaStreamNonBlocking);
        cudaEventCreateWithFlags(&evF, cudaEventDisableTiming);
        cudaEventCreateWithFlags(&evA, cudaEventDisableTiming);
        cudaEventCreateWithFlags(&evB1, cudaEventDisableTiming);
        cudaEventCreateWithFlags(&evB2, cudaEventDisableTiming);
    }
    cudaStream_t spine = 0;

    dim3 tbE(14, 16);
    dim3 tb2(7, 32);
    const int embBlocks = (N + 63) / 64;
    const int g4Blocks = (N + 127) / 128;
    const int aggBlocks = (N + 7) / 8;
    const int Esplit = ((E_ / 2 + 127) / 128) * 128;
    const int eg1Blocks = Esplit / 128;
    const int eg2Blocks = (E_ - Esplit + 127) / 128;
    const size_t smem146 = (size_t)(146 * D + 64 * 146) * sizeof(float);
    const size_t smemBig = (size_t)(D * D + 128 * D) * sizeof(float);
    cudaFuncSetAttribute(gemm70_kernel<146>, cudaFuncAttributeMaxDynamicSharedMemorySize, (int)smem146);
    cudaFuncSetAttribute(gemm4_kernel, cudaFuncAttributeMaxDynamicSharedMemorySize, (int)smemBig);
    cudaFuncSetAttribute(edgegemm_kernel<1, 1>, cudaFuncAttributeMaxDynamicSharedMemorySize, (int)smemBig);
    cudaFuncSetAttribute(edgegemm_kernel<0, 1>, cudaFuncAttributeMaxDynamicSharedMemorySize, (int)smemBig);
    cudaFuncSetAttribute(edgegemm_kernel<0, 0>, cudaFuncAttributeMaxDynamicSharedMemorySize, (int)smemBig);

    // ---- prologue: {emb -> gemm4_0} on sA  ||  {hist -> scan -> scatter -> uv} on sB ----
    cudaEventRecord(evF, spine);
    cudaStreamWaitEvent(sA, evF, 0);
    cudaStreamWaitEvent(sB, evF, 0);

    gemm70_kernel<146><<<embBlocks, tbE, smem146, sA>>>(nodes, Wemb_h, bemb_h, ph, N);
    gemm4_kernel<<<g4Blocks, tb2, smemBig, sA>>>(WA, bA, WB, bB, WDl, bDl, WEl, bEl,
                                                 nullptr, nullptr, 0, N);
    cudaEventRecord(evA, sA);

    hist_kernel<<<(E_ + 255) / 256, 256, 0, sB>>>(dst, E_);
    scan_kernel<<<1, 1024, 0, sB>>>(N, E_);
    scatter_sort_kernel<<<(E_ + 255) / 256, 256, 0, sB>>>(src, dst, ef, snorm_e, E_);
    uv_kernel<<<1, D, 0, sB>>>(Wemb_e, bemb_e, WC, bC);
    cudaEventRecord(evB1, sB);

    cudaStreamWaitEvent(spine, evA, 0);
    cudaStreamWaitEvent(spine, evB1, 0);

    agg_kernel<1, 0, 0><<<aggBlocks, 256, 0, spine>>>(snorm_n, N, 0);
    finalize_kernel<<<1, 2 * D, 0, spine>>>(Wemb_e, bemb_e, WC + 1 * D * D, bC + 1 * D,
                                            N, E_, 1);

    // ---- layers 1..3: gemm4 || (edgegemm chunk1, chunk2), agg pipelined ----
    for (int l = 1; l < 4; l++) {
        const float* wA = WA + l * D * D; const float* biA = bA + l * D;
        const float* wB = WB + l * D * D; const float* biB = bB + l * D;
        const float* wC = WC + l * D * D;
        const float* wD = WDl + l * D * D; const float* biD = bDl + l * D;
        const float* wE = WEl + l * D * D; const float* biE = bEl + l * D;

        cudaEventRecord(evF, spine);
        cudaStreamWaitEvent(sA, evF, 0);
        cudaStreamWaitEvent(sB, evF, 0);

        gemm4_kernel<<<g4Blocks, tb2, smemBig, sA>>>(wA, biA, wB, biB, wD, biD, wE, biE,
                                                     gh + (l - 1) * D, bh + (l - 1) * D, 1, N);
        cudaEventRecord(evA, sA);

        const float* eg = ge + (l - 1) * D;
        const float* eb = be + (l - 1) * D;
        if (l == 1) {
            edgegemm_kernel<1, 1><<<eg1Blocks, tb2, smemBig, sB>>>(wC, eg, eb, 0, Esplit);
            cudaEventRecord(evB1, sB);
            edgegemm_kernel<1, 1><<<eg2Blocks, tb2, smemBig, sB>>>(wC, eg, eb, Esplit, E_);
        } else if (l == 2) {
            edgegemm_kernel<0, 1><<<eg1Blocks, tb2, smemBig, sB>>>(wC, eg, eb, 0, Esplit);
            cudaEventRecord(evB1, sB);
            edgegemm_kernel<0, 1><<<eg2Blocks, tb2, smemBig, sB>>>(wC, eg, eb, Esplit, E_);
        } else {
            edgegemm_kernel<0, 0><<<eg1Blocks, tb2, smemBig, sB>>>(wC, eg, eb, 0, Esplit);
            cudaEventRecord(evB1, sB);
            edgegemm_kernel<0, 0><<<eg2Blocks, tb2, smemBig, sB>>>(wC, eg, eb, Esplit, E_);
        }
        cudaEventRecord(evB2, sB);

        // agg chunk1: nodes fully inside [0, Esplit)  — overlaps edgegemm chunk2
        cudaStreamWaitEvent(spine, evA, 0);
        cudaStreamWaitEvent(spine, evB1, 0);
        if (l == 3)
            agg_kernel<0, 1, 1><<<aggBlocks, 256, 0, spine>>>(snorm_n, N, Esplit);
        else
            agg_kernel<0, 0, 1><<<aggBlocks, 256, 0, spine>>>(snorm_n, N, Esplit);

        // agg chunk2: remaining nodes — needs all ce
        cudaStreamWaitEvent(spine, evB2, 0);
        if (l == 3) {
            agg_kernel<0, 1, 2><<<aggBlocks, 256, 0, spine>>>(snorm_n, N, Esplit);
            finalize_kernel<<<1, 2 * D, 0, spine>>>(Wemb_e, bemb_e, nullptr, nullptr, N, E_, 0);
        } else {
            agg_kernel<0, 0, 2><<<aggBlocks, 256, 0, spine>>>(snorm_n, N, Esplit);
            finalize_kernel<<<1, 2 * D, 0, spine>>>(Wemb_e, bemb_e, WC + (l + 1) * D * D,
                                                    bC + (l + 1) * D, N, E_, 1);
        }
    }

    // ---- readout ----
    zero_readout_kernel<<<(GG * D + 255) / 256, 256, 0, spine>>>();
    scatter_kernel<<<(N + 7) / 8, dim3(D, 8), 0, spine>>>(gid, gh + 3 * D, bh + 3 * D, N);
    mlp_kernel<<<1, GG, 0, spine>>>(W0, b0, W1, b1, W2, b2, out);
}

// round 14
// speedup vs baseline: 1.0283x; 1.0283x over previous
#include <cuda_runtime.h>
#include <math.h>

#define D 70
#define NMAX 50000
#define EMAX 800000
#define GG 128

// ---------------- device scratch ----------------
__device__ float g_h[NMAX * D];
__device__ float g_A[NMAX * D];
__device__ float g_B[NMAX * D];
__device__ float g_Dh[NMAX * D];
__device__ float g_Eh[NMAX * D];
__device__ float g_hraw[NMAX * D];
__device__ float g_S[EMAX * D];
__device__ float g_enew[EMAX * D];
__device__ float g_ce[EMAX * D];
__device__ float g_statsf[4][64][D];
__device__ float g_norm[4 * D];
__device__ float g_hg[GG * D];
__device__ float g_cnt[GG];
__device__ float g_u[D];
__device__ float g_v[D];
__device__ int g_cnt_n[NMAX];
__device__ int g_rowoff[NMAX + 1];
__device__ int g_psrc[EMAX];
__device__ float g_pef[EMAX];
__device__ float g_psn[EMAX];

// ---------------- packed fp32x2 helpers (sm_100+) ----------------
__device__ __forceinline__ unsigned long long pk2(float lo, float hi) {
    unsigned long long r;
    asm("mov.b64 %0, {%1, %2};" : "=l"(r) : "f"(lo), "f"(hi));
    return r;
}
__device__ __forceinline__ void ffma2(unsigned long long& d, unsigned long long a,
                                      unsigned long long b) {
    asm("fma.rn.f32x2 %0, %1, %2, %0;" : "+l"(d) : "l"(a), "l"(b));
}

// ---------------- sort: histogram / scan / scatter ----------------
__global__ void hist_kernel(const int* __restrict__ dst, int E_) {
    int i = blockIdx.x * blockDim.x + threadIdx.x;
    if (i < E_) atomicAdd(&g_cnt_n[dst[i]], 1);
}

__global__ void scan_kernel(int Nn, int E_) {
    __shared__ int s[1024];
    int t = threadIdx.x;
    int chunk = (Nn + 1023) / 1024;
    int begin = t * chunk, end = min(begin + chunk, Nn);
    int sum = 0;
    for (int i = begin; i < end; i++) sum += g_cnt_n[i];
    s[t] = sum;
    __syncthreads();
    for (int off = 1; off < 1024; off <<= 1) {
        int tmp = (t >= off) ? s[t - off] : 0;
        __syncthreads();
        s[t] += tmp;
        __syncthreads();
    }
    int acc = s[t] - sum;
    for (int i = begin; i < end; i++) {
        int c = g_cnt_n[i];
        g_rowoff[i] = acc;
        acc += c;
        g_cnt_n[i] = 0;
    }
    if (t == 0) g_rowoff[Nn] = E_;
}

__global__ void scatter_sort_kernel(const int* __restrict__ src, const int* __restrict__ dst,
                                    const float* __restrict__ ef, const float* __restrict__ sn,
                                    int E_) {
    int i = blockIdx.x * blockDim.x + threadIdx.x;
    if (i < E_) {
        int d = dst[i];
        int pos = g_rowoff[d] + atomicAdd(&g_cnt_n[d], 1);
        g_psrc[pos] = src[i];
        g_pef[pos] = ef[i];
        g_psn[pos] = sn[i];
    }
}

// ---------------- layer-0 rank-1 Ce precompute ----------------
__global__ void uv_kernel(const float* __restrict__ WembE, const float* __restrict__ bembE,
                          const float* __restrict__ WC, const float* __restrict__ bC) {
    int j = threadIdx.x;
    if (j >= D) return;
    float u = 0.f, v = 0.f;
    for (int k = 0; k < D; k++) {
        float w = WC[k * D + j];
        u += WembE[k] * w;
        v += bembE[k] * w;
    }
    g_u[j] = u;
    g_v[j] = v + bC[j];
}

// ---------------- embedding GEMM [N,146]@[146,70] ----------------
template <int K>
__global__ void gemm70_kernel(const float* __restrict__ X, const float* __restrict__ W,
                              const float* __restrict__ bias, float* __restrict__ Y, int M) {
    extern __shared__ float smem[];
    float* sW = smem;
    float* sX = smem + K * D;
    __shared__ float sb[D];
    const int tx = threadIdx.x, ty = threadIdx.y;
    const int tid = ty * 14 + tx;
    for (int i = tid; i < K * D; i += 224) sW[i] = W[i];
    if (tid < D) sb[tid] = bias[tid];
    __syncthreads();

    const int base = blockIdx.x * 64;
    const int cnt = min(64, M - base);
    for (int i = tid; i < cnt * K; i += 224) sX[i] = X[(size_t)base * K + i];
    __syncthreads();

    const int c0 = tx * 5, r0 = ty * 4;
    float acc[4][5];
#pragma unroll
    for (int r = 0; r < 4; r++)
#pragma unroll
        for (int c = 0; c < 5; c++) acc[r][c] = sb[c0 + c];

#pragma unroll 2
    for (int k = 0; k < K; k++) {
        float w0 = sW[k * D + c0 + 0], w1 = sW[k * D + c0 + 1], w2 = sW[k * D + c0 + 2];
        float w3 = sW[k * D + c0 + 3], w4 = sW[k * D + c0 + 4];
#pragma unroll
        for (int r = 0; r < 4; r++) {
            float xv = (r0 + r < cnt) ? sX[(r0 + r) * K + k] : 0.f;
            acc[r][0] += xv * w0; acc[r][1] += xv * w1; acc[r][2] += xv * w2;
            acc[r][3] += xv * w3; acc[r][4] += xv * w4;
        }
    }
#pragma unroll
    for (int r = 0; r < 4; r++) {
        int row = base + r0 + r;
        if (row < M) {
#pragma unroll
            for (int c = 0; c < 5; c++) Y[(size_t)row * D + c0 + c] = acc[r][c];
        }
    }
}

// ---------------- fused node kernel: optional h-update + 4 GEMMs (f32x2) ----------------
__global__ __launch_bounds__(224, 3) void gemm4_kernel(
    const float* __restrict__ WA, const float* __restrict__ bA,
    const float* __restrict__ WB, const float* __restrict__ bB,
    const float* __restrict__ WD, const float* __restrict__ bD,
    const float* __restrict__ WE, const float* __restrict__ bE,
    const float* __restrict__ hgam, const float* __restrict__ hbet,
    int fuse, int Nn) {
    extern __shared__ __align__(16) float dsm[];
    float* sW = dsm;              // 70*70
    float* sX = dsm + D * D;      // 128*70
    __shared__ float sb[D];
    __shared__ float sMu[D], sRs[D], sGa[D], sBe[D];
    const int tx = threadIdx.x, ty = threadIdx.y;
    const int tid = ty * 7 + tx;
    if (fuse && tid < D) {
        sMu[tid] = g_norm[tid];
        sRs[tid] = g_norm[D + tid];
        sGa[tid] = hgam[tid];
        sBe[tid] = hbet[tid];
    }
    const int base = blockIdx.x * 128;
    const int cnt = min(128, Nn - base);
    __syncthreads();
    for (int idx = tid; idx < cnt * D; idx += 224) {
        size_t gi = (size_t)base * D + idx;
        float v = g_h[gi];
        if (fuse) {
            int r = idx / D;
            int c = idx - r * D;
            float hr = g_hraw[gi];
            v += fmaxf((hr - sMu[c]) * sRs[c] * sGa[c] + sBe[c], 0.f);
            g_h[gi] = v;
        }
        sX[idx] = v;
    }
    if (cnt < 128)
        for (int idx = cnt * D + tid; idx < 128 * D; idx += 224) sX[idx] = 0.f;

    const float* Ws[4] = {WA, WB, WD, WE};
    const float* bs[4] = {bA, bB, bD, bE};
    float* outs[4] = {g_A, g_B, g_Dh, g_Eh};

    const int c0 = tx * 10;
    for (int m = 0; m < 4; m++) {
        __syncthreads();
        for (int i = tid; i < D * D; i += 224) sW[i] = Ws[m][i];
        if (tid < D) sb[tid] = bs[m][tid];
        __syncthreads();

        unsigned long long acc[4][5];
#pragma unroll
        for (int c = 0; c < 5; c++) {
            unsigned long long bp = pk2(sb[c0 + 2 * c], sb[c0 + 2 * c + 1]);
#pragma unroll
            for (int r = 0; r < 4; r++) acc[r][c] = bp;
        }

#pragma unroll 2
        for (int k = 0; k < D; k++) {
            unsigned long long w[5];
#pragma unroll
            for (int c = 0; c < 5; c++)
                w[c] = *(const unsigned long long*)&sW[k * D + c0 + 2 * c];
#pragma unroll
            for (int r = 0; r < 4; r++) {
                float xv = sX[(ty + 32 * r) * D + k];
                unsigned long long xp = pk2(xv, xv);
#pragma unroll
                for (int c = 0; c < 5; c++) ffma2(acc[r][c], xp, w[c]);
            }
        }
        float* out = outs[m];
#pragma unroll
        for (int r = 0; r < 4; r++) {
            int row = base + ty + 32 * r;
            if (row < Nn) {
#pragma unroll
                for (int c = 0; c < 5; c++)
                    *(unsigned long long*)&out[(size_t)row * D + c0 + 2 * c] = acc[r][c];
            }
        }
    }
}

// ---------------- streaming edge GEMM (f32x2): ce = S_new@WC + ef*u + v ----------------
template <int FIRST, int WRITE_S>
__global__ __launch_bounds__(224, 3) void edgegemm_kernel(
    const float* __restrict__ WC,
    const float* __restrict__ egam, const float* __restrict__ ebet, int E_) {
    extern __shared__ __align__(16) float dsm[];
    float* sW = dsm;             // 70*70
    float* sX = dsm + D * D;     // 128*70
    __shared__ float sef[128];
    __shared__ float su[D], sv[D], sMu[D], sRs[D], sGa[D], sBe[D];
    const int tx = threadIdx.x, ty = threadIdx.y;
    const int tid = ty * 7 + tx;
    for (int i = tid; i < D * D; i += 224) sW[i] = WC[i];
    if (tid < D) {
        su[tid] = g_u[tid];
        sv[tid] = g_v[tid];
        sMu[tid] = g_norm[2 * D + tid];
        sRs[tid] = g_norm[3 * D + tid];
        sGa[tid] = egam[tid];
        sBe[tid] = ebet[tid];
    }
    __syncthreads();

    const int base = blockIdx.x * 128;
    const int cnt = min(128, E_ - base);
    for (int idx = tid; idx < cnt * D; idx += 224) {
        size_t gi = (size_t)base * D + idx;
        int r = idx / D;
        int c = idx - r * D;
        float R = fmaxf((g_enew[gi] - sMu[c]) * sRs[c] * sGa[c] + sBe[c], 0.f);
        float Sv = FIRST ? R : (g_S[gi] + R);
        sX[idx] = Sv;
        if (WRITE_S) g_S[gi] = Sv;
    }
    if (cnt < 128)
        for (int idx = cnt * D + tid; idx < 128 * D; idx += 224) sX[idx] = 0.f;
    for (int i = tid; i < 128; i += 224) sef[i] = (i < cnt) ? g_pef[base + i] : 0.f;
    __syncthreads();

    const int c0 = tx * 10;
    unsigned long long acc[4][5];
#pragma unroll
    for (int r = 0; r < 4; r++) {
        float efv = sef[ty + 32 * r];
#pragma unroll
        for (int c = 0; c < 5; c++)
            acc[r][c] = pk2(sv[c0 + 2 * c] + efv * su[c0 + 2 * c],
                            sv[c0 + 2 * c + 1] + efv * su[c0 + 2 * c + 1]);
    }

#pragma unroll 2
    for (int k = 0; k < D; k++) {
        unsigned long long w[5];
#pragma unroll
        for (int c = 0; c < 5; c++)
            w[c] = *(const unsigned long long*)&sW[k * D + c0 + 2 * c];
#pragma unroll
        for (int r = 0; r < 4; r++) {
            float xv = sX[(ty + 32 * r) * D + k];
            unsigned long long xp = pk2(xv, xv);
#pragma unroll
            for (int c = 0; c < 5; c++) ffma2(acc[r][c], xp, w[c]);
        }
    }
#pragma unroll
    for (int r = 0; r < 4; r++) {
        int ei = base + ty + 32 * r;
        if (ei < E_) {
#pragma unroll
            for (int c = 0; c < 5; c++)
                *(unsigned long long*)&g_ce[(size_t)ei * D + c0 + 2 * c] = acc[r][c];
        }
    }
}

// ---------------- node aggregation: TWO warps per node, 3 cols/lane ----------------
// Block 256 = 8 warps = 4 nodes x 2 warps; each warp handles half the node's edges;
// partial num/den combined via smem, halving the serial per-node latency chain.
template <int RANK1, int LAST>
__global__ __launch_bounds__(256) void agg_kernel(const float* __restrict__ snorm_n, int Nn) {
    const int lane = threadIdx.x & 31;
    const int w = threadIdx.x >> 5;        // 0..7
    const int slot = w >> 1;               // node slot 0..3
    const int half = w & 1;
    const int n = blockIdx.x * 4 + slot;

    { int i = blockIdx.x * 256 + threadIdx.x; if (i < Nn) g_cnt_n[i] = 0; }

    __shared__ float sStat[4][D];
    __shared__ float sPart[4][6][32];
    for (int i = threadIdx.x; i < 4 * D; i += 256) ((float*)sStat)[i] = 0.f;
    __syncthreads();

    const int j0 = lane, j1 = lane + 32;
    const bool m2 = lane < (D - 64);
    const int j2 = m2 ? lane + 64 : lane;

    const bool valid = (n < Nn);
    float num0 = 0, den0 = 0, num1 = 0, den1 = 0, num2 = 0, den2 = 0;
    float lsE0 = 0, lqE0 = 0, lsE1 = 0, lqE1 = 0, lsE2 = 0, lqE2 = 0;
    size_t nb = 0;

    if (valid) {
        float u0, v0, u1, v1, u2, v2;
        if (RANK1) {
            u0 = g_u[j0]; v0 = g_v[j0];
            u1 = g_u[j1]; v1 = g_v[j1];
            u2 = g_u[j2]; v2 = g_v[j2];
        }
        nb = (size_t)n * D;
        const float eh0 = g_Eh[nb + j0], eh1 = g_Eh[nb + j1], eh2 = g_Eh[nb + j2];
        const int e0 = g_rowoff[n], e1 = g_rowoff[n + 1];
        const int emid = (e0 + e1 + 1) >> 1;
        const int es = half ? emid : e0;
        const int ee = half ? e1 : emid;
        for (int e = es; e < ee; e++) {
            int s = g_psrc[e];
            size_t sb = (size_t)s * D;
            size_t eb = (size_t)e * D;
            float ce0, ce1, ce2;
            if (RANK1) {
                float ef = g_pef[e];
                ce0 = ef * u0 + v0; ce1 = ef * u1 + v1; ce2 = ef * u2 + v2;
            } else {
                ce0 = g_ce[eb + j0]; ce1 = g_ce[eb + j1]; ce2 = g_ce[eb + j2];
            }
            float dh0 = g_Dh[sb + j0], dh1 = g_Dh[sb + j1], dh2 = g_Dh[sb + j2];
            float bb0 = g_B[sb + j0], bb1 = g_B[sb + j1], bb2 = g_B[sb + j2];
            float en0 = ce0 + dh0 + eh0;
            float en1 = ce1 + dh1 + eh1;
            float en2 = ce2 + dh2 + eh2;
            float sg0 = 1.f / (1.f + __expf(-en0));
            float sg1 = 1.f / (1.f + __expf(-en1));
            float sg2 = 1.f / (1.f + __expf(-en2));
            num0 += bb0 * sg0; den0 += sg0;
            num1 += bb1 * sg1; den1 += sg1;
            num2 += bb2 * sg2; den2 += sg2;
            if (!LAST) {
                float sn = g_psn[e];
                float s0 = en0 * sn, s1 = en1 * sn, s2 = en2 * sn;
                g_enew[eb + j0] = s0;
                g_enew[eb + j1] = s1;
                if (m2) g_enew[eb + j2] = s2;
                lsE0 += s0; lqE0 += s0 * s0;
                lsE1 += s1; lqE1 += s1 * s1;
                lsE2 += s2; lqE2 += s2 * s2;
            }
        }
    }

    if (half == 1) {
        sPart[slot][0][lane] = num0; sPart[slot][1][lane] = den0;
        sPart[slot][2][lane] = num1; sPart[slot][3][lane] = den1;
        sPart[slot][4][lane] = num2; sPart[slot][5][lane] = den2;
    }
    if (valid && !LAST) {
        atomicAdd(&sStat[2][j0], lsE0); atomicAdd(&sStat[3][j0], lqE0);
        atomicAdd(&sStat[2][j1], lsE1); atomicAdd(&sStat[3][j1], lqE1);
        if (m2) { atomicAdd(&sStat[2][j2], lsE2); atomicAdd(&sStat[3][j2], lqE2); }
    }
    __syncthreads();

    if (valid && half == 0) {
        num0 += sPart[slot][0][lane]; den0 += sPart[slot][1][lane];
        num1 += sPart[slot][2][lane]; den1 += sPart[slot][3][lane];
        num2 += sPart[slot][4][lane]; den2 += sPart[slot][5][lane];
        float snn = snorm_n[n];
        float hv0 = (g_A[nb + j0] + num0 / (den0 + 1e-6f)) * snn;
        float hv1 = (g_A[nb + j1] + num1 / (den1 + 1e-6f)) * snn;
        float hv2 = (g_A[nb + j2] + num2 / (den2 + 1e-6f)) * snn;
        g_hraw[nb + j0] = hv0;
        g_hraw[nb + j1] = hv1;
        if (m2) g_hraw[nb + j2] = hv2;
        atomicAdd(&sStat[0][j0], hv0); atomicAdd(&sStat[1][j0], hv0 * hv0);
        atomicAdd(&sStat[0][j1], hv1); atomicAdd(&sStat[1][j1], hv1 * hv1);
        if (m2) { atomicAdd(&sStat[0][j2], hv2); atomicAdd(&sStat[1][j2], hv2 * hv2); }
    }
    __syncthreads();

    const int slot64 = blockIdx.x & 63;
    const int lim = LAST ? 2 * D : 4 * D;
    for (int i = threadIdx.x; i < lim; i += 256) {
        int st = i / D, j = i - st * D;
        float val = sStat[st][j];
        if (val != 0.f) atomicAdd(&g_statsf[st][slot64][j], val);
    }
}

// ---------------- finalize: reduce stat shards -> norms; next layer's u,v ----------------
__global__ void finalize_kernel(const float* __restrict__ WembE, const float* __restrict__ bembE,
                                const float* __restrict__ WCn, const float* __restrict__ bCn,
                                int Nn, int E_, int haveE) {
    int t = threadIdx.x;
    if (t < D) {
        float sh = 0.f, sq = 0.f;
        for (int s = 0; s < 64; s++) {
            sh += g_statsf[0][s][t]; g_statsf[0][s][t] = 0.f;
            sq += g_statsf[1][s][t]; g_statsf[1][s][t] = 0.f;
        }
        float mu = sh / Nn;
        float var = sq / Nn - mu * mu;
        g_norm[t] = mu;
        g_norm[D + t] = rsqrtf(fmaxf(var, 0.f) + 1e-5f);
        if (WCn) {
            float u = 0.f, v = 0.f;
            for (int k = 0; k < D; k++) {
                float w = WCn[k * D + t];
                u += WembE[k] * w;
                v += bembE[k] * w;
            }
            g_u[t] = u;
            g_v[t] = v + bCn[t];
        }
    } else if (t < 2 * D && haveE) {
        int j = t - D;
        float se = 0.f, sq = 0.f;
        for (int s = 0; s < 64; s++) {
            se += g_statsf[2][s][j]; g_statsf[2][s][j] = 0.f;
            sq += g_statsf[3][s][j]; g_statsf[3][s][j] = 0.f;
        }
        float mu = se / E_;
        float var = sq / E_ - mu * mu;
        g_norm[2 * D + j] = mu;
        g_norm[3 * D + j] = rsqrtf(fmaxf(var, 0.f) + 1e-5f);
    }
}

// ---------------- readout ----------------
__global__ void zero_readout_kernel() {
    int i = blockIdx.x * blockDim.x + threadIdx.x;
    if (i < GG * D) g_hg[i] = 0.f;
    if (i < GG) g_cnt[i] = 0.f;
}

__global__ void scatter_kernel(const int* __restrict__ gid,
                               const float* __restrict__ hgam, const float* __restrict__ hbet,
                               int Nn) {
    int j = threadIdx.x;
    float mu = g_norm[j], rs = g_norm[D + j], ga = hgam[j], bb = hbet[j];
    for (int row = blockIdx.x * 8 + threadIdx.y; row < Nn; row += gridDim.x * 8) {
        size_t idx = (size_t)row * D + j;
        float v = g_h[idx] + fmaxf((g_hraw[idx] - mu) * rs * ga + bb, 0.f);
        int g = gid[row];
        atomicAdd(&g_hg[g * D + j], v);
        if (j == 0) atomicAdd(&g_cnt[g], 1.f);
    }
}

__global__ void mlp_kernel(const float* __restrict__ W0, const float* __restrict__ b0,
                           const float* __restrict__ W1, const float* __restrict__ b1,
                           const float* __restrict__ W2, const float* __restrict__ b2,
                           float* __restrict__ out) {
    int g = threadIdx.x;
    if (g >= GG) return;
    float cnt = fmaxf(g_cnt[g], 1.f);
    float x[D];
#pragma unroll
    for (int k = 0; k < D; k++) x[k] = g_hg[g * D + k] / cnt;
    float y0[35];
#pragma unroll
    for (int o = 0; o < 35; o++) {
        float s = b0[o];
#pragma unroll
        for (int k = 0; k < D; k++) s += x[k] * W0[k * 35 + o];
        y0[o] = fmaxf(s, 0.f);
    }
    float y1[17];
#pragma unroll
    for (int o = 0; o < 17; o++) {
        float s = b1[o];
#pragma unroll
        for (int k = 0; k < 35; k++) s += y0[k] * W1[k * 17 + o];
        y1[o] = fmaxf(s, 0.f);
    }
#pragma unroll
    for (int o = 0; o < 10; o++) {
        float s = b2[o];
#pragma unroll
        for (int k = 0; k < 17; k++) s += y1[k] * W2[k * 10 + o];
        out[g * 10 + o] = s;
    }
}

// ---------------- host ----------------
extern "C" void kernel_launch(void* const* d_in, const int* in_sizes, int n_in,
                              void* d_out, int out_size) {
    const float* nodes   = (const float*)d_in[0];
    const float* ef      = (const float*)d_in[1];
    const float* snorm_n = (const float*)d_in[2];
    const float* snorm_e = (const float*)d_in[3];
    const int N = in_sizes[2];
    const int E_ = in_sizes[3];

    const int *src, *dst, *gid;
    const float *Wemb_h, *bemb_h, *Wemb_e, *bemb_e;
    const float *WA, *bA, *WB, *bB, *WC, *bC, *WDl, *bDl, *WEl, *bEl;
    const float *gh, *bh, *ge, *be, *W0, *b0, *W1, *b1, *W2, *b2;

    if (in_sizes[4] == E_) {
        src = (const int*)d_in[4]; dst = (const int*)d_in[5]; gid = (const int*)d_in[6];
        Wemb_h = (const float*)d_in[7];  bemb_h = (const float*)d_in[8];
        Wemb_e = (const float*)d_in[9];  bemb_e = (const float*)d_in[10];
        WA = (const float*)d_in[11]; bA = (const float*)d_in[12];
        WB = (const float*)d_in[13]; bB = (const float*)d_in[14];
        WC = (const float*)d_in[15]; bC = (const float*)d_in[16];
        WDl = (const float*)d_in[17]; bDl = (const float*)d_in[18];
        WEl = (const float*)d_in[19]; bEl = (const float*)d_in[20];
        gh = (const float*)d_in[21]; bh = (const float*)d_in[22];
        ge = (const float*)d_in[23]; be = (const float*)d_in[24];
        W0 = (const float*)d_in[25]; b0 = (const float*)d_in[26];
        W1 = (const float*)d_in[27]; b1 = (const float*)d_in[28];
        W2 = (const float*)d_in[29]; b2 = (const float*)d_in[30];
    } else {
        Wemb_h = (const float*)d_in[4];  bemb_h = (const float*)d_in[5];
        Wemb_e = (const float*)d_in[6];  bemb_e = (const float*)d_in[7];
        WA = (const float*)d_in[8];  bA = (const float*)d_in[9];
        WB = (const float*)d_in[10]; bB = (const float*)d_in[11];
        WC = (const float*)d_in[12]; bC = (const float*)d_in[13];
        WDl = (const float*)d_in[14]; bDl = (const float*)d_in[15];
        WEl = (const float*)d_in[16]; bEl = (const float*)d_in[17];
        gh = (const float*)d_in[18]; bh = (const float*)d_in[19];
        ge = (const float*)d_in[20]; be = (const float*)d_in[21];
        W0 = (const float*)d_in[22]; b0 = (const float*)d_in[23];
        W1 = (const float*)d_in[24]; b1 = (const float*)d_in[25];
        W2 = (const float*)d_in[26]; b2 = (const float*)d_in[27];
        src = (const int*)d_in[28]; dst = (const int*)d_in[29]; gid = (const int*)d_in[30];
    }
    float* out = (float*)d_out;

    float* ph;
    cudaGetSymbolAddress((void**)&ph, g_h);

    static cudaStream_t sA = nullptr, sB = nullptr;
    static cudaEvent_t evF = nullptr, evA = nullptr, evB = nullptr;
    if (sA == nullptr) {
        cudaStreamCreateWithFlags(&sA, cudaStreamNonBlocking);
        cudaStreamCreateWithFlags(&sB, cudaStreamNonBlocking);
        cudaEventCreateWithFlags(&evF, cudaEventDisableTiming);
        cudaEventCreateWithFlags(&evA, cudaEventDisableTiming);
        cudaEventCreateWithFlags(&evB, cudaEventDisableTiming);
    }
    cudaStream_t spine = 0;

    dim3 tbE(14, 16);
    dim3 tb2(7, 32);
    const int embBlocks = (N + 63) / 64;
    const int g4Blocks = (N + 127) / 128;
    const int egBlocks = (E_ + 127) / 128;
    const int aggBlocks = (N + 3) / 4;
    const size_t smem146 = (size_t)(146 * D + 64 * 146) * sizeof(float);
    const size_t smemBig = (size_t)(D * D + 128 * D) * sizeof(float);
    cudaFuncSetAttribute(gemm70_kernel<146>, cudaFuncAttributeMaxDynamicSharedMemorySize, (int)smem146);
    cudaFuncSetAttribute(gemm4_kernel, cudaFuncAttributeMaxDynamicSharedMemorySize, (int)smemBig);
    cudaFuncSetAttribute(edgegemm_kernel<1, 1>, cudaFuncAttributeMaxDynamicSharedMemorySize, (int)smemBig);
    cudaFuncSetAttribute(edgegemm_kernel<0, 1>, cudaFuncAttributeMaxDynamicSharedMemorySize, (int)smemBig);
    cudaFuncSetAttribute(edgegemm_kernel<0, 0>, cudaFuncAttributeMaxDynamicSharedMemorySize, (int)smemBig);

    // ---- prologue: {emb -> gemm4_0} on sA  ||  {hist -> scan -> scatter -> uv} on sB ----
    cudaEventRecord(evF, spine);
    cudaStreamWaitEvent(sA, evF, 0);
    cudaStreamWaitEvent(sB, evF, 0);

    gemm70_kernel<146><<<embBlocks, tbE, smem146, sA>>>(nodes, Wemb_h, bemb_h, ph, N);
    gemm4_kernel<<<g4Blocks, tb2, smemBig, sA>>>(WA, bA, WB, bB, WDl, bDl, WEl, bEl,
                                                 nullptr, nullptr, 0, N);
    cudaEventRecord(evA, sA);

    hist_kernel<<<(E_ + 255) / 256, 256, 0, sB>>>(dst, E_);
    scan_kernel<<<1, 1024, 0, sB>>>(N, E_);
    scatter_sort_kernel<<<(E_ + 255) / 256, 256, 0, sB>>>(src, dst, ef, snorm_e, E_);
    uv_kernel<<<1, D, 0, sB>>>(Wemb_e, bemb_e, WC, bC);
    cudaEventRecord(evB, sB);

    cudaStreamWaitEvent(spine, evA, 0);
    cudaStreamWaitEvent(spine, evB, 0);

    agg_kernel<1, 0><<<aggBlocks, 256, 0, spine>>>(snorm_n, N);
    finalize_kernel<<<1, 2 * D, 0, spine>>>(Wemb_e, bemb_e, WC + 1 * D * D, bC + 1 * D,
                                            N, E_, 1);

    // ---- layers 1..3: gemm4 || edgegemm, then agg -> finalize ----
    for (int l = 1; l < 4; l++) {
        const float* wA = WA + l * D * D; const float* biA = bA + l * D;
        const float* wB = WB + l * D * D; const float* biB = bB + l * D;
        const float* wC = WC + l * D * D;
        const float* wD = WDl + l * D * D; const float* biD = bDl + l * D;
        const float* wE = WEl + l * D * D; const float* biE = bEl + l * D;

        cudaEventRecord(evF, spine);
        cudaStreamWaitEvent(sA, evF, 0);
        cudaStreamWaitEvent(sB, evF, 0);

        gemm4_kernel<<<g4Blocks, tb2, smemBig, sA>>>(wA, biA, wB, biB, wD, biD, wE, biE,
                                                     gh + (l - 1) * D, bh + (l - 1) * D, 1, N);
        cudaEventRecord(evA, sA);

        const float* eg = ge + (l - 1) * D;
        const float* eb = be + (l - 1) * D;
        if (l == 1)
            edgegemm_kernel<1, 1><<<egBlocks, tb2, smemBig, sB>>>(wC, eg, eb, E_);
        else if (l == 2)
            edgegemm_kernel<0, 1><<<egBlocks, tb2, smemBig, sB>>>(wC, eg, eb, E_);
        else
            edgegemm_kernel<0, 0><<<egBlocks, tb2, smemBig, sB>>>(wC, eg, eb, E_);
        cudaEventRecord(evB, sB);

        cudaStreamWaitEvent(spine, evA, 0);
        cudaStreamWaitEvent(spine, evB, 0);

        if (l == 3) {
            agg_kernel<0, 1><<<aggBlocks, 256, 0, spine>>>(snorm_n, N);
            finalize_kernel<<<1, 2 * D, 0, spine>>>(Wemb_e, bemb_e, nullptr, nullptr, N, E_, 0);
        } else {
            agg_kernel<0, 0><<<aggBlocks, 256, 0, spine>>>(snorm_n, N);
            finalize_kernel<<<1, 2 * D, 0, spine>>>(Wemb_e, bemb_e, WC + (l + 1) * D * D,
                                                    bC + (l + 1) * D, N, E_, 1);
        }
    }

    // ---- readout ----
    zero_readout_kernel<<<(GG * D + 255) / 256, 256, 0, spine>>>();
    scatter_kernel<<<(N + 7) / 8, dim3(D, 8), 0, spine>>>(gid, gh + 3 * D, bh + 3 * D, N);
    mlp_kernel<<<1, GG, 0, spine>>>(W0, b0, W1, b1, W2, b2, out);
}

// round 15
// speedup vs baseline: 1.0377x; 1.0091x over previous
#include <cuda_runtime.h>
#include <math.h>

#define D 70
#define NMAX 50000
#define EMAX 800000
#define GG 128

// ---------------- device scratch ----------------
__device__ float g_h[NMAX * D];
__device__ float g_A[NMAX * D];
__device__ float g_B[NMAX * D];
__device__ float g_Dh[NMAX * D];
__device__ float g_Eh[NMAX * D];
__device__ float g_hraw[NMAX * D];
__device__ float g_S[EMAX * D];
__device__ float g_enew[EMAX * D];
__device__ float g_ce[EMAX * D];
__device__ float g_statsf[4][64][D];
__device__ float g_norm[4 * D];
__device__ float g_hg[GG * D];
__device__ float g_cnt[GG];
__device__ float g_u[D];
__device__ float g_v[D];
__device__ int g_cnt_n[NMAX];
__device__ int g_rowoff[NMAX + 1];
__device__ int g_psrc[EMAX];
__device__ float g_pef[EMAX];
__device__ float g_psn[EMAX];

// ---------------- packed fp32x2 helpers (sm_100+) ----------------
__device__ __forceinline__ unsigned long long pk2(float lo, float hi) {
    unsigned long long r;
    asm("mov.b64 %0, {%1, %2};" : "=l"(r) : "f"(lo), "f"(hi));
    return r;
}
__device__ __forceinline__ void ffma2(unsigned long long& d, unsigned long long a,
                                      unsigned long long b) {
    asm("fma.rn.f32x2 %0, %1, %2, %0;" : "+l"(d) : "l"(a), "l"(b));
}

// ---------------- sort: histogram / scan / scatter ----------------
__global__ void hist_kernel(const int* __restrict__ dst, int E_) {
    int i = blockIdx.x * blockDim.x + threadIdx.x;
    if (i < E_) atomicAdd(&g_cnt_n[dst[i]], 1);
}

__global__ void scan_kernel(int Nn, int E_) {
    __shared__ int s[1024];
    int t = threadIdx.x;
    int chunk = (Nn + 1023) / 1024;
    int begin = t * chunk, end = min(begin + chunk, Nn);
    int sum = 0;
    for (int i = begin; i < end; i++) sum += g_cnt_n[i];
    s[t] = sum;
    __syncthreads();
    for (int off = 1; off < 1024; off <<= 1) {
        int tmp = (t >= off) ? s[t - off] : 0;
        __syncthreads();
        s[t] += tmp;
        __syncthreads();
    }
    int acc = s[t] - sum;
    for (int i = begin; i < end; i++) {
        int c = g_cnt_n[i];
        g_rowoff[i] = acc;
        acc += c;
        g_cnt_n[i] = 0;
    }
    if (t == 0) g_rowoff[Nn] = E_;
}

__global__ void scatter_sort_kernel(const int* __restrict__ src, const int* __restrict__ dst,
                                    const float* __restrict__ ef, const float* __restrict__ sn,
                                    int E_) {
    int i = blockIdx.x * blockDim.x + threadIdx.x;
    if (i < E_) {
        int d = dst[i];
        int pos = g_rowoff[d] + atomicAdd(&g_cnt_n[d], 1);
        g_psrc[pos] = src[i];
        g_pef[pos] = ef[i];
        g_psn[pos] = sn[i];
    }
}

// ---------------- layer-0 rank-1 Ce precompute ----------------
__global__ void uv_kernel(const float* __restrict__ WembE, const float* __restrict__ bembE,
                          const float* __restrict__ WC, const float* __restrict__ bC) {
    int j = threadIdx.x;
    if (j >= D) return;
    float u = 0.f, v = 0.f;
    for (int k = 0; k < D; k++) {
        float w = WC[k * D + j];
        u += WembE[k] * w;
        v += bembE[k] * w;
    }
    g_u[j] = u;
    g_v[j] = v + bC[j];
}

// ---------------- embedding GEMM [N,146]@[146,70] ----------------
template <int K>
__global__ void gemm70_kernel(const float* __restrict__ X, const float* __restrict__ W,
                              const float* __restrict__ bias, float* __restrict__ Y, int M) {
    extern __shared__ float smem[];
    float* sW = smem;
    float* sX = smem + K * D;
    __shared__ float sb[D];
    const int tx = threadIdx.x, ty = threadIdx.y;
    const int tid = ty * 14 + tx;
    for (int i = tid; i < K * D; i += 224) sW[i] = W[i];
    if (tid < D) sb[tid] = bias[tid];
    __syncthreads();

    const int base = blockIdx.x * 64;
    const int cnt = min(64, M - base);
    for (int i = tid; i < cnt * K; i += 224) sX[i] = X[(size_t)base * K + i];
    __syncthreads();

    const int c0 = tx * 5, r0 = ty * 4;
    float acc[4][5];
#pragma unroll
    for (int r = 0; r < 4; r++)
#pragma unroll
        for (int c = 0; c < 5; c++) acc[r][c] = sb[c0 + c];

#pragma unroll 2
    for (int k = 0; k < K; k++) {
        float w0 = sW[k * D + c0 + 0], w1 = sW[k * D + c0 + 1], w2 = sW[k * D + c0 + 2];
        float w3 = sW[k * D + c0 + 3], w4 = sW[k * D + c0 + 4];
#pragma unroll
        for (int r = 0; r < 4; r++) {
            float xv = (r0 + r < cnt) ? sX[(r0 + r) * K + k] : 0.f;
            acc[r][0] += xv * w0; acc[r][1] += xv * w1; acc[r][2] += xv * w2;
            acc[r][3] += xv * w3; acc[r][4] += xv * w4;
        }
    }
#pragma unroll
    for (int r = 0; r < 4; r++) {
        int row = base + r0 + r;
        if (row < M) {
#pragma unroll
            for (int c = 0; c < 5; c++) Y[(size_t)row * D + c0 + c] = acc[r][c];
        }
    }
}

// ---------------- fused node kernel: optional h-update + 4 GEMMs (f32x2) ----------------
__global__ __launch_bounds__(224, 3) void gemm4_kernel(
    const float* __restrict__ WA, const float* __restrict__ bA,
    const float* __restrict__ WB, const float* __restrict__ bB,
    const float* __restrict__ WD, const float* __restrict__ bD,
    const float* __restrict__ WE, const float* __restrict__ bE,
    const float* __restrict__ hgam, const float* __restrict__ hbet,
    int fuse, int Nn) {
    extern __shared__ __align__(16) float dsm[];
    float* sW = dsm;              // 70*70
    float* sX = dsm + D * D;      // 128*70
    __shared__ float sb[D];
    __shared__ float sMu[D], sRs[D], sGa[D], sBe[D];
    const int tx = threadIdx.x, ty = threadIdx.y;
    const int tid = ty * 7 + tx;
    if (fuse && tid < D) {
        sMu[tid] = g_norm[tid];
        sRs[tid] = g_norm[D + tid];
        sGa[tid] = hgam[tid];
        sBe[tid] = hbet[tid];
    }
    const int base = blockIdx.x * 128;
    const int cnt = min(128, Nn - base);
    __syncthreads();
    for (int idx = tid; idx < cnt * D; idx += 224) {
        size_t gi = (size_t)base * D + idx;
        float v = g_h[gi];
        if (fuse) {
            int r = idx / D;
            int c = idx - r * D;
            float hr = g_hraw[gi];
            v += fmaxf((hr - sMu[c]) * sRs[c] * sGa[c] + sBe[c], 0.f);
            g_h[gi] = v;
        }
        sX[idx] = v;
    }
    if (cnt < 128)
        for (int idx = cnt * D + tid; idx < 128 * D; idx += 224) sX[idx] = 0.f;

    const float* Ws[4] = {WA, WB, WD, WE};
    const float* bs[4] = {bA, bB, bD, bE};
    float* outs[4] = {g_A, g_B, g_Dh, g_Eh};

    const int c0 = tx * 10;
    for (int m = 0; m < 4; m++) {
        __syncthreads();
        for (int i = tid; i < D * D; i += 224) sW[i] = Ws[m][i];
        if (tid < D) sb[tid] = bs[m][tid];
        __syncthreads();

        unsigned long long acc[4][5];
#pragma unroll
        for (int c = 0; c < 5; c++) {
            unsigned long long bp = pk2(sb[c0 + 2 * c], sb[c0 + 2 * c + 1]);
#pragma unroll
            for (int r = 0; r < 4; r++) acc[r][c] = bp;
        }

#pragma unroll 2
        for (int k = 0; k < D; k++) {
            unsigned long long w[5];
#pragma unroll
            for (int c = 0; c < 5; c++)
                w[c] = *(const unsigned long long*)&sW[k * D + c0 + 2 * c];
#pragma unroll
            for (int r = 0; r < 4; r++) {
                float xv = sX[(ty + 32 * r) * D + k];
                unsigned long long xp = pk2(xv, xv);
#pragma unroll
                for (int c = 0; c < 5; c++) ffma2(acc[r][c], xp, w[c]);
            }
        }
        float* out = outs[m];
#pragma unroll
        for (int r = 0; r < 4; r++) {
            int row = base + ty + 32 * r;
            if (row < Nn) {
#pragma unroll
                for (int c = 0; c < 5; c++)
                    *(unsigned long long*)&out[(size_t)row * D + c0 + 2 * c] = acc[r][c];
            }
        }
    }
}

// ---------------- streaming edge GEMM (f32x2): ce = S_new@WC + ef*u + v ----------------
template <int FIRST, int WRITE_S>
__global__ __launch_bounds__(224, 3) void edgegemm_kernel(
    const float* __restrict__ WC,
    const float* __restrict__ egam, const float* __restrict__ ebet, int E_) {
    extern __shared__ __align__(16) float dsm[];
    float* sW = dsm;             // 70*70
    float* sX = dsm + D * D;     // 128*70
    __shared__ float sef[128];
    __shared__ float su[D], sv[D], sMu[D], sRs[D], sGa[D], sBe[D];
    const int tx = threadIdx.x, ty = threadIdx.y;
    const int tid = ty * 7 + tx;
    for (int i = tid; i < D * D; i += 224) sW[i] = WC[i];
    if (tid < D) {
        su[tid] = g_u[tid];
        sv[tid] = g_v[tid];
        sMu[tid] = g_norm[2 * D + tid];
        sRs[tid] = g_norm[3 * D + tid];
        sGa[tid] = egam[tid];
        sBe[tid] = ebet[tid];
    }
    __syncthreads();

    const int base = blockIdx.x * 128;
    const int cnt = min(128, E_ - base);
    for (int idx = tid; idx < cnt * D; idx += 224) {
        size_t gi = (size_t)base * D + idx;
        int r = idx / D;
        int c = idx - r * D;
        float R = fmaxf((g_enew[gi] - sMu[c]) * sRs[c] * sGa[c] + sBe[c], 0.f);
        float Sv = FIRST ? R : (g_S[gi] + R);
        sX[idx] = Sv;
        if (WRITE_S) g_S[gi] = Sv;
    }
    if (cnt < 128)
        for (int idx = cnt * D + tid; idx < 128 * D; idx += 224) sX[idx] = 0.f;
    for (int i = tid; i < 128; i += 224) sef[i] = (i < cnt) ? g_pef[base + i] : 0.f;
    __syncthreads();

    const int c0 = tx * 10;
    unsigned long long acc[4][5];
#pragma unroll
    for (int r = 0; r < 4; r++) {
        float efv = sef[ty + 32 * r];
#pragma unroll
        for (int c = 0; c < 5; c++)
            acc[r][c] = pk2(sv[c0 + 2 * c] + efv * su[c0 + 2 * c],
                            sv[c0 + 2 * c + 1] + efv * su[c0 + 2 * c + 1]);
    }

#pragma unroll 2
    for (int k = 0; k < D; k++) {
        unsigned long long w[5];
#pragma unroll
        for (int c = 0; c < 5; c++)
            w[c] = *(const unsigned long long*)&sW[k * D + c0 + 2 * c];
#pragma unroll
        for (int r = 0; r < 4; r++) {
            float xv = sX[(ty + 32 * r) * D + k];
            unsigned long long xp = pk2(xv, xv);
#pragma unroll
            for (int c = 0; c < 5; c++) ffma2(acc[r][c], xp, w[c]);
        }
    }
#pragma unroll
    for (int r = 0; r < 4; r++) {
        int ei = base + ty + 32 * r;
        if (ei < E_) {
#pragma unroll
            for (int c = 0; c < 5; c++)
                *(unsigned long long*)&g_ce[(size_t)ei * D + c0 + 2 * c] = acc[r][c];
        }
    }
}

// ---------------- node aggregation: warp-per-node, 3 cols/lane, edge unroll-2 ----------------
template <int RANK1, int LAST>
__global__ __launch_bounds__(256) void agg_kernel(const float* __restrict__ snorm_n, int Nn) {
    const int lane = threadIdx.x & 31;
    const int w = threadIdx.x >> 5;
    const int n = blockIdx.x * 8 + w;

    { int i = blockIdx.x * 256 + threadIdx.x; if (i < Nn) g_cnt_n[i] = 0; }

    __shared__ float sStat[4][D];
    for (int i = threadIdx.x; i < 4 * D; i += 256) ((float*)sStat)[i] = 0.f;
    __syncthreads();

    const int j0 = lane, j1 = lane + 32;
    const bool m2 = lane < (D - 64);
    const int j2 = m2 ? lane + 64 : lane;

    if (n < Nn) {
        float u0, v0, u1, v1, u2, v2;
        if (RANK1) {
            u0 = g_u[j0]; v0 = g_v[j0];
            u1 = g_u[j1]; v1 = g_v[j1];
            u2 = g_u[j2]; v2 = g_v[j2];
        }
        const size_t nb = (size_t)n * D;
        const float eh0 = g_Eh[nb + j0], eh1 = g_Eh[nb + j1], eh2 = g_Eh[nb + j2];
        const int e0 = g_rowoff[n], e1 = g_rowoff[n + 1];
        // accumulator set A (even-position edges) and B (odd-position edges)
        float nA0 = 0, dA0 = 0, nA1 = 0, dA1 = 0, nA2 = 0, dA2 = 0;
        float nB0 = 0, dB0 = 0, nB1 = 0, dB1 = 0, nB2 = 0, dB2 = 0;
        float lsE0 = 0, lqE0 = 0, lsE1 = 0, lqE1 = 0, lsE2 = 0, lqE2 = 0;
        int e = e0;
        for (; e + 2 <= e1; e += 2) {
            int sa = g_psrc[e], sb_ = g_psrc[e + 1];
            size_t sba = (size_t)sa * D, sbb = (size_t)sb_ * D;
            size_t eba = (size_t)e * D, ebb = (size_t)(e + 1) * D;
            float ceA0, ceA1, ceA2, ceB0, ceB1, ceB2;
            if (RANK1) {
                float efa = g_pef[e], efb = g_pef[e + 1];
                ceA0 = efa * u0 + v0; ceA1 = efa * u1 + v1; ceA2 = efa * u2 + v2;
                ceB0 = efb * u0 + v0; ceB1 = efb * u1 + v1; ceB2 = efb * u2 + v2;
            } else {
                ceA0 = g_ce[eba + j0]; ceA1 = g_ce[eba + j1]; ceA2 = g_ce[eba + j2];
                ceB0 = g_ce[ebb + j0]; ceB1 = g_ce[ebb + j1]; ceB2 = g_ce[ebb + j2];
            }
            float dhA0 = g_Dh[sba + j0], dhA1 = g_Dh[sba + j1], dhA2 = g_Dh[sba + j2];
            float dhB0 = g_Dh[sbb + j0], dhB1 = g_Dh[sbb + j1], dhB2 = g_Dh[sbb + j2];
            float bbA0 = g_B[sba + j0], bbA1 = g_B[sba + j1], bbA2 = g_B[sba + j2];
            float bbB0 = g_B[sbb + j0], bbB1 = g_B[sbb + j1], bbB2 = g_B[sbb + j2];
            float enA0 = ceA0 + dhA0 + eh0, enA1 = ceA1 + dhA1 + eh1, enA2 = ceA2 + dhA2 + eh2;
            float enB0 = ceB0 + dhB0 + eh0, enB1 = ceB1 + dhB1 + eh1, enB2 = ceB2 + dhB2 + eh2;
            float sgA0 = 1.f / (1.f + __expf(-enA0));
            float sgA1 = 1.f / (1.f + __expf(-enA1));
            float sgA2 = 1.f / (1.f + __expf(-enA2));
            float sgB0 = 1.f / (1.f + __expf(-enB0));
            float sgB1 = 1.f / (1.f + __expf(-enB1));
            float sgB2 = 1.f / (1.f + __expf(-enB2));
            nA0 += bbA0 * sgA0; dA0 += sgA0;
            nA1 += bbA1 * sgA1; dA1 += sgA1;
            nA2 += bbA2 * sgA2; dA2 += sgA2;
            nB0 += bbB0 * sgB0; dB0 += sgB0;
            nB1 += bbB1 * sgB1; dB1 += sgB1;
            nB2 += bbB2 * sgB2; dB2 += sgB2;
            if (!LAST) {
                float snA = g_psn[e], snB = g_psn[e + 1];
                float sA0 = enA0 * snA, sA1 = enA1 * snA, sA2 = enA2 * snA;
                float sB0 = enB0 * snB, sB1 = enB1 * snB, sB2 = enB2 * snB;
                g_enew[eba + j0] = sA0;
                g_enew[eba + j1] = sA1;
                if (m2) g_enew[eba + j2] = sA2;
                g_enew[ebb + j0] = sB0;
                g_enew[ebb + j1] = sB1;
                if (m2) g_enew[ebb + j2] = sB2;
                lsE0 += sA0 + sB0; lqE0 += sA0 * sA0 + sB0 * sB0;
                lsE1 += sA1 + sB1; lqE1 += sA1 * sA1 + sB1 * sB1;
                lsE2 += sA2 + sB2; lqE2 += sA2 * sA2 + sB2 * sB2;
            }
        }
        if (e < e1) {
            int sa = g_psrc[e];
            size_t sba = (size_t)sa * D;
            size_t eba = (size_t)e * D;
            float ce0, ce1, ce2;
            if (RANK1) {
                float efa = g_pef[e];
                ce0 = efa * u0 + v0; ce1 = efa * u1 + v1; ce2 = efa * u2 + v2;
            } else {
                ce0 = g_ce[eba + j0]; ce1 = g_ce[eba + j1]; ce2 = g_ce[eba + j2];
            }
            float en0 = ce0 + g_Dh[sba + j0] + eh0;
            float en1 = ce1 + g_Dh[sba + j1] + eh1;
            float en2 = ce2 + g_Dh[sba + j2] + eh2;
            float sg0 = 1.f / (1.f + __expf(-en0));
            float sg1 = 1.f / (1.f + __expf(-en1));
            float sg2 = 1.f / (1.f + __expf(-en2));
            nA0 += g_B[sba + j0] * sg0; dA0 += sg0;
            nA1 += g_B[sba + j1] * sg1; dA1 += sg1;
            nA2 += g_B[sba + j2] * sg2; dA2 += sg2;
            if (!LAST) {
                float sn = g_psn[e];
                float s0 = en0 * sn, s1 = en1 * sn, s2 = en2 * sn;
                g_enew[eba + j0] = s0;
                g_enew[eba + j1] = s1;
                if (m2) g_enew[eba + j2] = s2;
                lsE0 += s0; lqE0 += s0 * s0;
                lsE1 += s1; lqE1 += s1 * s1;
                lsE2 += s2; lqE2 += s2 * s2;
            }
        }
        float num0 = nA0 + nB0, den0 = dA0 + dB0;
        float num1 = nA1 + nB1, den1 = dA1 + dB1;
        float num2 = nA2 + nB2, den2 = dA2 + dB2;
        float snn = snorm_n[n];
        float hv0 = (g_A[nb + j0] + num0 / (den0 + 1e-6f)) * snn;
        float hv1 = (g_A[nb + j1] + num1 / (den1 + 1e-6f)) * snn;
        float hv2 = (g_A[nb + j2] + num2 / (den2 + 1e-6f)) * snn;
        g_hraw[nb + j0] = hv0;
        g_hraw[nb + j1] = hv1;
        if (m2) g_hraw[nb + j2] = hv2;
        atomicAdd(&sStat[0][j0], hv0); atomicAdd(&sStat[1][j0], hv0 * hv0);
        atomicAdd(&sStat[0][j1], hv1); atomicAdd(&sStat[1][j1], hv1 * hv1);
        if (m2) { atomicAdd(&sStat[0][j2], hv2); atomicAdd(&sStat[1][j2], hv2 * hv2); }
        if (!LAST) {
            atomicAdd(&sStat[2][j0], lsE0); atomicAdd(&sStat[3][j0], lqE0);
            atomicAdd(&sStat[2][j1], lsE1); atomicAdd(&sStat[3][j1], lqE1);
            if (m2) { atomicAdd(&sStat[2][j2], lsE2); atomicAdd(&sStat[3][j2], lqE2); }
        }
    }
    __syncthreads();
    const int slot = blockIdx.x & 63;
    const int lim = LAST ? 2 * D : 4 * D;
    for (int i = threadIdx.x; i < lim; i += 256) {
        int st = i / D, j = i - st * D;
        float val = sStat[st][j];
        if (val != 0.f) atomicAdd(&g_statsf[st][slot][j], val);
    }
}

// ---------------- finalize: reduce stat shards -> norms; next layer's u,v ----------------
__global__ void finalize_kernel(const float* __restrict__ WembE, const float* __restrict__ bembE,
                                const float* __restrict__ WCn, const float* __restrict__ bCn,
                                int Nn, int E_, int haveE) {
    int t = threadIdx.x;
    if (t < D) {
        float sh = 0.f, sq = 0.f;
        for (int s = 0; s < 64; s++) {
            sh += g_statsf[0][s][t]; g_statsf[0][s][t] = 0.f;
            sq += g_statsf[1][s][t]; g_statsf[1][s][t] = 0.f;
        }
        float mu = sh / Nn;
        float var = sq / Nn - mu * mu;
        g_norm[t] = mu;
        g_norm[D + t] = rsqrtf(fmaxf(var, 0.f) + 1e-5f);
        if (WCn) {
            float u = 0.f, v = 0.f;
            for (int k = 0; k < D; k++) {
                float w = WCn[k * D + t];
                u += WembE[k] * w;
                v += bembE[k] * w;
            }
            g_u[t] = u;
            g_v[t] = v + bCn[t];
        }
    } else if (t < 2 * D && haveE) {
        int j = t - D;
        float se = 0.f, sq = 0.f;
        for (int s = 0; s < 64; s++) {
            se += g_statsf[2][s][j]; g_statsf[2][s][j] = 0.f;
            sq += g_statsf[3][s][j]; g_statsf[3][s][j] = 0.f;
        }
        float mu = se / E_;
        float var = sq / E_ - mu * mu;
        g_norm[2 * D + j] = mu;
        g_norm[3 * D + j] = rsqrtf(fmaxf(var, 0.f) + 1e-5f);
    }
}

// ---------------- readout ----------------
__global__ void zero_readout_kernel() {
    int i = blockIdx.x * blockDim.x + threadIdx.x;
    if (i < GG * D) g_hg[i] = 0.f;
    if (i < GG) g_cnt[i] = 0.f;
}

__global__ void scatter_kernel(const int* __restrict__ gid,
                               const float* __restrict__ hgam, const float* __restrict__ hbet,
                               int Nn) {
    int j = threadIdx.x;
    float mu = g_norm[j], rs = g_norm[D + j], ga = hgam[j], bb = hbet[j];
    for (int row = blockIdx.x * 8 + threadIdx.y; row < Nn; row += gridDim.x * 8) {
        size_t idx = (size_t)row * D + j;
        float v = g_h[idx] + fmaxf((g_hraw[idx] - mu) * rs * ga + bb, 0.f);
        int g = gid[row];
        atomicAdd(&g_hg[g * D + j], v);
        if (j == 0) atomicAdd(&g_cnt[g], 1.f);
    }
}

__global__ void mlp_kernel(const float* __restrict__ W0, const float* __restrict__ b0,
                           const float* __restrict__ W1, const float* __restrict__ b1,
                           const float* __restrict__ W2, const float* __restrict__ b2,
                           float* __restrict__ out) {
    int g = threadIdx.x;
    if (g >= GG) return;
    float cnt = fmaxf(g_cnt[g], 1.f);
    float x[D];
#pragma unroll
    for (int k = 0; k < D; k++) x[k] = g_hg[g * D + k] / cnt;
    float y0[35];
#pragma unroll
    for (int o = 0; o < 35; o++) {
        float s = b0[o];
#pragma unroll
        for (int k = 0; k < D; k++) s += x[k] * W0[k * 35 + o];
        y0[o] = fmaxf(s, 0.f);
    }
    float y1[17];
#pragma unroll
    for (int o = 0; o < 17; o++) {
        float s = b1[o];
#pragma unroll
        for (int k = 0; k < 35; k++) s += y0[k] * W1[k * 17 + o];
        y1[o] = fmaxf(s, 0.f);
    }
#pragma unroll
    for (int o = 0; o < 10; o++) {
        float s = b2[o];
#pragma unroll
        for (int k = 0; k < 17; k++) s += y1[k] * W2[k * 10 + o];
        out[g * 10 + o] = s;
    }
}

// ---------------- host ----------------
extern "C" void kernel_launch(void* const* d_in, const int* in_sizes, int n_in,
                              void* d_out, int out_size) {
    const float* nodes   = (const float*)d_in[0];
    const float* ef      = (const float*)d_in[1];
    const float* snorm_n = (const float*)d_in[2];
    const float* snorm_e = (const float*)d_in[3];
    const int N = in_sizes[2];
    const int E_ = in_sizes[3];

    const int *src, *dst, *gid;
    const float *Wemb_h, *bemb_h, *Wemb_e, *bemb_e;
    const float *WA, *bA, *WB, *bB, *WC, *bC, *WDl, *bDl, *WEl, *bEl;
    const float *gh, *bh, *ge, *be, *W0, *b0, *W1, *b1, *W2, *b2;

    if (in_sizes[4] == E_) {
        src = (const int*)d_in[4]; dst = (const int*)d_in[5]; gid = (const int*)d_in[6];
        Wemb_h = (const float*)d_in[7];  bemb_h = (const float*)d_in[8];
        Wemb_e = (const float*)d_in[9];  bemb_e = (const float*)d_in[10];
        WA = (const float*)d_in[11]; bA = (const float*)d_in[12];
        WB = (const float*)d_in[13]; bB = (const float*)d_in[14];
        WC = (const float*)d_in[15]; bC = (const float*)d_in[16];
        WDl = (const float*)d_in[17]; bDl = (const float*)d_in[18];
        WEl = (const float*)d_in[19]; bEl = (const float*)d_in[20];
        gh = (const float*)d_in[21]; bh = (const float*)d_in[22];
        ge = (const float*)d_in[23]; be = (const float*)d_in[24];
        W0 = (const float*)d_in[25]; b0 = (const float*)d_in[26];
        W1 = (const float*)d_in[27]; b1 = (const float*)d_in[28];
        W2 = (const float*)d_in[29]; b2 = (const float*)d_in[30];
    } else {
        Wemb_h = (const float*)d_in[4];  bemb_h = (const float*)d_in[5];
        Wemb_e = (const float*)d_in[6];  bemb_e = (const float*)d_in[7];
        WA = (const float*)d_in[8];  bA = (const float*)d_in[9];
        WB = (const float*)d_in[10]; bB = (const float*)d_in[11];
        WC = (const float*)d_in[12]; bC = (const float*)d_in[13];
        WDl = (const float*)d_in[14]; bDl = (const float*)d_in[15];
        WEl = (const float*)d_in[16]; bEl = (const float*)d_in[17];
        gh = (const float*)d_in[18]; bh = (const float*)d_in[19];
        ge = (const float*)d_in[20]; be = (const float*)d_in[21];
        W0 = (const float*)d_in[22]; b0 = (const float*)d_in[23];
        W1 = (const float*)d_in[24]; b1 = (const float*)d_in[25];
        W2 = (const float*)d_in[26]; b2 = (const float*)d_in[27];
        src = (const int*)d_in[28]; dst = (const int*)d_in[29]; gid = (const int*)d_in[30];
    }
    float* out = (float*)d_out;

    float* ph;
    cudaGetSymbolAddress((void**)&ph, g_h);

    static cudaStream_t sA = nullptr, sB = nullptr;
    static cudaEvent_t evF = nullptr, evA = nullptr, evB = nullptr;
    if (sA == nullptr) {
        cudaStreamCreateWithFlags(&sA, cudaStreamNonBlocking);
        cudaStreamCreateWithFlags(&sB, cudaStreamNonBlocking);
        cudaEventCreateWithFlags(&evF, cudaEventDisableTiming);
        cudaEventCreateWithFlags(&evA, cudaEventDisableTiming);
        cudaEventCreateWithFlags(&evB, cudaEventDisableTiming);
    }
    cudaStream_t spine = 0;

    dim3 tbE(14, 16);
    dim3 tb2(7, 32);
    const int embBlocks = (N + 63) / 64;
    const int g4Blocks = (N + 127) / 128;
    const int egBlocks = (E_ + 127) / 128;
    const int aggBlocks = (N + 7) / 8;
    const size_t smem146 = (size_t)(146 * D + 64 * 146) * sizeof(float);
    const size_t smemBig = (size_t)(D * D + 128 * D) * sizeof(float);
    cudaFuncSetAttribute(gemm70_kernel<146>, cudaFuncAttributeMaxDynamicSharedMemorySize, (int)smem146);
    cudaFuncSetAttribute(gemm4_kernel, cudaFuncAttributeMaxDynamicSharedMemorySize, (int)smemBig);
    cudaFuncSetAttribute(edgegemm_kernel<1, 1>, cudaFuncAttributeMaxDynamicSharedMemorySize, (int)smemBig);
    cudaFuncSetAttribute(edgegemm_kernel<0, 1>, cudaFuncAttributeMaxDynamicSharedMemorySize, (int)smemBig);
    cudaFuncSetAttribute(edgegemm_kernel<0, 0>, cudaFuncAttributeMaxDynamicSharedMemorySize, (int)smemBig);

    // ---- prologue: {emb -> gemm4_0} on sA  ||  {hist -> scan -> scatter -> uv} on sB ----
    cudaEventRecord(evF, spine);
    cudaStreamWaitEvent(sA, evF, 0);
    cudaStreamWaitEvent(sB, evF, 0);

    gemm70_kernel<146><<<embBlocks, tbE, smem146, sA>>>(nodes, Wemb_h, bemb_h, ph, N);
    gemm4_kernel<<<g4Blocks, tb2, smemBig, sA>>>(WA, bA, WB, bB, WDl, bDl, WEl, bEl,
                                                 nullptr, nullptr, 0, N);
    cudaEventRecord(evA, sA);

    hist_kernel<<<(E_ + 255) / 256, 256, 0, sB>>>(dst, E_);
    scan_kernel<<<1, 1024, 0, sB>>>(N, E_);
    scatter_sort_kernel<<<(E_ + 255) / 256, 256, 0, sB>>>(src, dst, ef, snorm_e, E_);
    uv_kernel<<<1, D, 0, sB>>>(Wemb_e, bemb_e, WC, bC);
    cudaEventRecord(evB, sB);

    cudaStreamWaitEvent(spine, evA, 0);
    cudaStreamWaitEvent(spine, evB, 0);

    agg_kernel<1, 0><<<aggBlocks, 256, 0, spine>>>(snorm_n, N);
    finalize_kernel<<<1, 2 * D, 0, spine>>>(Wemb_e, bemb_e, WC + 1 * D * D, bC + 1 * D,
                                            N, E_, 1);

    // ---- layers 1..3: gemm4 || edgegemm, then agg -> finalize ----
    for (int l = 1; l < 4; l++) {
        const float* wA = WA + l * D * D; const float* biA = bA + l * D;
        const float* wB = WB + l * D * D; const float* biB = bB + l * D;
        const float* wC = WC + l * D * D;
        const float* wD = WDl + l * D * D; const float* biD = bDl + l * D;
        const float* wE = WEl + l * D * D; const float* biE = bEl + l * D;

        cudaEventRecord(evF, spine);
        cudaStreamWaitEvent(sA, evF, 0);
        cudaStreamWaitEvent(sB, evF, 0);

        gemm4_kernel<<<g4Blocks, tb2, smemBig, sA>>>(wA, biA, wB, biB, wD, biD, wE, biE,
                                                     gh + (l - 1) * D, bh + (l - 1) * D, 1, N);
        cudaEventRecord(evA, sA);

        const float* eg = ge + (l - 1) * D;
        const float* eb = be + (l - 1) * D;
        if (l == 1)
            edgegemm_kernel<1, 1><<<egBlocks, tb2, smemBig, sB>>>(wC, eg, eb, E_);
        else if (l == 2)
            edgegemm_kernel<0, 1><<<egBlocks, tb2, smemBig, sB>>>(wC, eg, eb, E_);
        else
            edgegemm_kernel<0, 0><<<egBlocks, tb2, smemBig, sB>>>(wC, eg, eb, E_);
        cudaEventRecord(evB, sB);

        cudaStreamWaitEvent(spine, evA, 0);
        cudaStreamWaitEvent(spine, evB, 0);

        if (l == 3) {
            agg_kernel<0, 1><<<aggBlocks, 256, 0, spine>>>(snorm_n, N);
            finalize_kernel<<<1, 2 * D, 0, spine>>>(Wemb_e, bemb_e, nullptr, nullptr, N, E_, 0);
        } else {
            agg_kernel<0, 0><<<aggBlocks, 256, 0, spine>>>(snorm_n, N);
            finalize_kernel<<<1, 2 * D, 0, spine>>>(Wemb_e, bemb_e, WC + (l + 1) * D * D,
                                                    bC + (l + 1) * D, N, E_, 1);
        }
    }

    // ---- readout ----
    zero_readout_kernel<<<(GG * D + 255) / 256, 256, 0, spine>>>();
    scatter_kernel<<<(N + 7) / 8, dim3(D, 8), 0, spine>>>(gid, gh + 3 * D, bh + 3 * D, N);
    mlp_kernel<<<1, GG, 0, spine>>>(W0, b0, W1, b1, W2, b2, out);
}

// round 16
// speedup vs baseline: 1.0698x; 1.0310x over previous
#include <cuda_runtime.h>
#include <math.h>

#define D 70
#define NMAX 50000
#define EMAX 800000
#define GG 128

// ---------------- device scratch ----------------
__device__ float g_h[NMAX * D];
__device__ float g_A[NMAX * D];
__device__ float g_DB[NMAX * 2 * D];   // interleaved per node: [B row (70) | Dh row (70)]
__device__ float g_Eh[NMAX * D];
__device__ float g_hraw[NMAX * D];
__device__ float g_S[EMAX * D];
__device__ float g_enew[EMAX * D];
__device__ float g_ce[EMAX * D];
__device__ float g_statsf[4][64][D];
__device__ float g_norm[4 * D];
__device__ float g_hg[GG * D];
__device__ float g_cnt[GG];
__device__ float g_u[D];
__device__ float g_v[D];
__device__ int g_cnt_n[NMAX];
__device__ int g_rowoff[NMAX + 1];
__device__ int g_blockoff[64];
__device__ int g_psrc[EMAX];
__device__ float g_pef[EMAX];
__device__ float g_psn[EMAX];

// ---------------- packed fp32x2 helpers (sm_100+) ----------------
__device__ __forceinline__ unsigned long long pk2(float lo, float hi) {
    unsigned long long r;
    asm("mov.b64 %0, {%1, %2};" : "=l"(r) : "f"(lo), "f"(hi));
    return r;
}
__device__ __forceinline__ void ffma2(unsigned long long& d, unsigned long long a,
                                      unsigned long long b) {
    asm("fma.rn.f32x2 %0, %1, %2, %0;" : "+l"(d) : "l"(a), "l"(b));
}

// ---------------- sort: histogram / multi-block scan / scatter ----------------
__global__ void hist_kernel(const int* __restrict__ dst, int E_) {
    int i = blockIdx.x * blockDim.x + threadIdx.x;
    if (i < E_) atomicAdd(&g_cnt_n[dst[i]], 1);
}

// block-local exclusive scan -> g_rowoff (partial), block totals -> g_blockoff (raw)
__global__ void scan1_kernel(int Nn) {
    __shared__ int s[1024];
    int t = threadIdx.x;
    int i = blockIdx.x * 1024 + t;
    int v = (i < Nn) ? g_cnt_n[i] : 0;
    s[t] = v;
    __syncthreads();
    for (int off = 1; off < 1024; off <<= 1) {
        int tmp = (t >= off) ? s[t - off] : 0;
        __syncthreads();
        s[t] += tmp;
        __syncthreads();
    }
    if (i < Nn) g_rowoff[i] = s[t] - v;   // block-local exclusive
    if (t == 1023) g_blockoff[blockIdx.x] = s[1023];
}

// serial scan of <=64 block sums
__global__ void scan2_kernel(int nb) {
    if (threadIdx.x == 0) {
        int acc = 0;
        for (int b = 0; b < nb; b++) {
            int tmp = g_blockoff[b];
            g_blockoff[b] = acc;
            acc += tmp;
        }
    }
}

// add block offsets, reset cursors, set sentinel
__global__ void scan3_kernel(int Nn, int E_) {
    int i = blockIdx.x * 1024 + threadIdx.x;
    if (i < Nn) {
        g_rowoff[i] += g_blockoff[blockIdx.x];
        g_cnt_n[i] = 0;   // scatter cursor
    }
    if (i == 0) g_rowoff[Nn] = E_;
}

__global__ void scatter_sort_kernel(const int* __restrict__ src, const int* __restrict__ dst,
                                    const float* __restrict__ ef, const float* __restrict__ sn,
                                    int E_) {
    int i = blockIdx.x * blockDim.x + threadIdx.x;
    if (i < E_) {
        int d = dst[i];
        int pos = g_rowoff[d] + atomicAdd(&g_cnt_n[d], 1);
        g_psrc[pos] = src[i];
        g_pef[pos] = ef[i];
        g_psn[pos] = sn[i];
    }
}

// ---------------- layer-0 rank-1 Ce precompute ----------------
__global__ void uv_kernel(const float* __restrict__ WembE, const float* __restrict__ bembE,
                          const float* __restrict__ WC, const float* __restrict__ bC) {
    int j = threadIdx.x;
    if (j >= D) return;
    float u = 0.f, v = 0.f;
    for (int k = 0; k < D; k++) {
        float w = WC[k * D + j];
        u += WembE[k] * w;
        v += bembE[k] * w;
    }
    g_u[j] = u;
    g_v[j] = v + bC[j];
}

// ---------------- embedding GEMM [N,146]@[146,70] ----------------
template <int K>
__global__ void gemm70_kernel(const float* __restrict__ X, const float* __restrict__ W,
                              const float* __restrict__ bias, float* __restrict__ Y, int M) {
    extern __shared__ float smem[];
    float* sW = smem;
    float* sX = smem + K * D;
    __shared__ float sb[D];
    const int tx = threadIdx.x, ty = threadIdx.y;
    const int tid = ty * 14 + tx;
    for (int i = tid; i < K * D; i += 224) sW[i] = W[i];
    if (tid < D) sb[tid] = bias[tid];
    __syncthreads();

    const int base = blockIdx.x * 64;
    const int cnt = min(64, M - base);
    for (int i = tid; i < cnt * K; i += 224) sX[i] = X[(size_t)base * K + i];
    __syncthreads();

    const int c0 = tx * 5, r0 = ty * 4;
    float acc[4][5];
#pragma unroll
    for (int r = 0; r < 4; r++)
#pragma unroll
        for (int c = 0; c < 5; c++) acc[r][c] = sb[c0 + c];

#pragma unroll 2
    for (int k = 0; k < K; k++) {
        float w0 = sW[k * D + c0 + 0], w1 = sW[k * D + c0 + 1], w2 = sW[k * D + c0 + 2];
        float w3 = sW[k * D + c0 + 3], w4 = sW[k * D + c0 + 4];
#pragma unroll
        for (int r = 0; r < 4; r++) {
            float xv = (r0 + r < cnt) ? sX[(r0 + r) * K + k] : 0.f;
            acc[r][0] += xv * w0; acc[r][1] += xv * w1; acc[r][2] += xv * w2;
            acc[r][3] += xv * w3; acc[r][4] += xv * w4;
        }
    }
#pragma unroll
    for (int r = 0; r < 4; r++) {
        int row = base + r0 + r;
        if (row < M) {
#pragma unroll
            for (int c = 0; c < 5; c++) Y[(size_t)row * D + c0 + c] = acc[r][c];
        }
    }
}

// ---------------- fused node kernel: optional h-update + 4 GEMMs (f32x2) ----------------
__global__ __launch_bounds__(224, 3) void gemm4_kernel(
    const float* __restrict__ WA, const float* __restrict__ bA,
    const float* __restrict__ WB, const float* __restrict__ bB,
    const float* __restrict__ WD, const float* __restrict__ bD,
    const float* __restrict__ WE, const float* __restrict__ bE,
    const float* __restrict__ hgam, const float* __restrict__ hbet,
    int fuse, int Nn) {
    extern __shared__ __align__(16) float dsm[];
    float* sW = dsm;              // 70*70
    float* sX = dsm + D * D;      // 128*70
    __shared__ float sb[D];
    __shared__ float sMu[D], sRs[D], sGa[D], sBe[D];
    const int tx = threadIdx.x, ty = threadIdx.y;
    const int tid = ty * 7 + tx;
    if (fuse && tid < D) {
        sMu[tid] = g_norm[tid];
        sRs[tid] = g_norm[D + tid];
        sGa[tid] = hgam[tid];
        sBe[tid] = hbet[tid];
    }
    const int base = blockIdx.x * 128;
    const int cnt = min(128, Nn - base);
    __syncthreads();
    for (int idx = tid; idx < cnt * D; idx += 224) {
        size_t gi = (size_t)base * D + idx;
        float v = g_h[gi];
        if (fuse) {
            int r = idx / D;
            int c = idx - r * D;
            float hr = g_hraw[gi];
            v += fmaxf((hr - sMu[c]) * sRs[c] * sGa[c] + sBe[c], 0.f);
            g_h[gi] = v;
        }
        sX[idx] = v;
    }
    if (cnt < 128)
        for (int idx = cnt * D + tid; idx < 128 * D; idx += 224) sX[idx] = 0.f;

    // outputs: A -> g_A (stride 70); B -> g_DB+0 (stride 140); Dh -> g_DB+70 (stride 140); Eh -> g_Eh
    const float* Ws[4] = {WA, WB, WD, WE};
    const float* bs[4] = {bA, bB, bD, bE};
    float* outs[4] = {g_A, g_DB, g_DB + D, g_Eh};
    const int strides[4] = {D, 2 * D, 2 * D, D};

    const int c0 = tx * 10;
    for (int m = 0; m < 4; m++) {
        __syncthreads();
        for (int i = tid; i < D * D; i += 224) sW[i] = Ws[m][i];
        if (tid < D) sb[tid] = bs[m][tid];
        __syncthreads();

        unsigned long long acc[4][5];
#pragma unroll
        for (int c = 0; c < 5; c++) {
            unsigned long long bp = pk2(sb[c0 + 2 * c], sb[c0 + 2 * c + 1]);
#pragma unroll
            for (int r = 0; r < 4; r++) acc[r][c] = bp;
        }

#pragma unroll 2
        for (int k = 0; k < D; k++) {
            unsigned long long w[5];
#pragma unroll
            for (int c = 0; c < 5; c++)
                w[c] = *(const unsigned long long*)&sW[k * D + c0 + 2 * c];
#pragma unroll
            for (int r = 0; r < 4; r++) {
                float xv = sX[(ty + 32 * r) * D + k];
                unsigned long long xp = pk2(xv, xv);
#pragma unroll
                for (int c = 0; c < 5; c++) ffma2(acc[r][c], xp, w[c]);
            }
        }
        float* out = outs[m];
        const int stride = strides[m];
#pragma unroll
        for (int r = 0; r < 4; r++) {
            int row = base + ty + 32 * r;
            if (row < Nn) {
#pragma unroll
                for (int c = 0; c < 5; c++)
                    *(unsigned long long*)&out[(size_t)row * stride + c0 + 2 * c] = acc[r][c];
            }
        }
    }
}

// ---------------- streaming edge GEMM (f32x2): ce = S_new@WC + ef*u + v ----------------
template <int FIRST, int WRITE_S>
__global__ __launch_bounds__(224, 3) void edgegemm_kernel(
    const float* __restrict__ WC,
    const float* __restrict__ egam, const float* __restrict__ ebet, int E_) {
    extern __shared__ __align__(16) float dsm[];
    float* sW = dsm;             // 70*70
    float* sX = dsm + D * D;     // 128*70
    __shared__ float sef[128];
    __shared__ float su[D], sv[D], sMu[D], sRs[D], sGa[D], sBe[D];
    const int tx = threadIdx.x, ty = threadIdx.y;
    const int tid = ty * 7 + tx;
    for (int i = tid; i < D * D; i += 224) sW[i] = WC[i];
    if (tid < D) {
        su[tid] = g_u[tid];
        sv[tid] = g_v[tid];
        sMu[tid] = g_norm[2 * D + tid];
        sRs[tid] = g_norm[3 * D + tid];
        sGa[tid] = egam[tid];
        sBe[tid] = ebet[tid];
    }
    __syncthreads();

    const int base = blockIdx.x * 128;
    const int cnt = min(128, E_ - base);
    for (int idx = tid; idx < cnt * D; idx += 224) {
        size_t gi = (size_t)base * D + idx;
        int r = idx / D;
        int c = idx - r * D;
        float R = fmaxf((g_enew[gi] - sMu[c]) * sRs[c] * sGa[c] + sBe[c], 0.f);
        float Sv = FIRST ? R : (g_S[gi] + R);
        sX[idx] = Sv;
        if (WRITE_S) g_S[gi] = Sv;
    }
    if (cnt < 128)
        for (int idx = cnt * D + tid; idx < 128 * D; idx += 224) sX[idx] = 0.f;
    for (int i = tid; i < 128; i += 224) sef[i] = (i < cnt) ? g_pef[base + i] : 0.f;
    __syncthreads();

    const int c0 = tx * 10;
    unsigned long long acc[4][5];
#pragma unroll
    for (int r = 0; r < 4; r++) {
        float efv = sef[ty + 32 * r];
#pragma unroll
        for (int c = 0; c < 5; c++)
            acc[r][c] = pk2(sv[c0 + 2 * c] + efv * su[c0 + 2 * c],
                            sv[c0 + 2 * c + 1] + efv * su[c0 + 2 * c + 1]);
    }

#pragma unroll 2
    for (int k = 0; k < D; k++) {
        unsigned long long w[5];
#pragma unroll
        for (int c = 0; c < 5; c++)
            w[c] = *(const unsigned long long*)&sW[k * D + c0 + 2 * c];
#pragma unroll
        for (int r = 0; r < 4; r++) {
            float xv = sX[(ty + 32 * r) * D + k];
            unsigned long long xp = pk2(xv, xv);
#pragma unroll
            for (int c = 0; c < 5; c++) ffma2(acc[r][c], xp, w[c]);
        }
    }
#pragma unroll
    for (int r = 0; r < 4; r++) {
        int ei = base + ty + 32 * r;
        if (ei < E_) {
#pragma unroll
            for (int c = 0; c < 5; c++)
                *(unsigned long long*)&g_ce[(size_t)ei * D + c0 + 2 * c] = acc[r][c];
        }
    }
}

// ---------------- node aggregation: warp-per-node, 3 cols/lane ----------------
template <int RANK1, int LAST>
__global__ __launch_bounds__(256) void agg_kernel(const float* __restrict__ snorm_n, int Nn) {
    const int lane = threadIdx.x & 31;
    const int w = threadIdx.x >> 5;
    const int n = blockIdx.x * 8 + w;

    { int i = blockIdx.x * 256 + threadIdx.x; if (i < Nn) g_cnt_n[i] = 0; }

    __shared__ float sStat[4][D];
    for (int i = threadIdx.x; i < 4 * D; i += 256) ((float*)sStat)[i] = 0.f;
    __syncthreads();

    const int j0 = lane, j1 = lane + 32;
    const bool m2 = lane < (D - 64);
    const int j2 = m2 ? lane + 64 : lane;

    if (n < Nn) {
        float u0, v0, u1, v1, u2, v2;
        if (RANK1) {
            u0 = g_u[j0]; v0 = g_v[j0];
            u1 = g_u[j1]; v1 = g_v[j1];
            u2 = g_u[j2]; v2 = g_v[j2];
        }
        const size_t nb = (size_t)n * D;
        const float eh0 = g_Eh[nb + j0], eh1 = g_Eh[nb + j1], eh2 = g_Eh[nb + j2];
        const int e0 = g_rowoff[n], e1 = g_rowoff[n + 1];
        float num0 = 0, den0 = 0, num1 = 0, den1 = 0, num2 = 0, den2 = 0;
        float lsE0 = 0, lqE0 = 0, lsE1 = 0, lqE1 = 0, lsE2 = 0, lqE2 = 0;
        for (int e = e0; e < e1; e++) {
            int s = g_psrc[e];
            size_t sb2 = (size_t)s * 2 * D;   // [B | Dh] interleaved row
            size_t eb = (size_t)e * D;
            float ce0, ce1, ce2;
            if (RANK1) {
                float ef = g_pef[e];
                ce0 = ef * u0 + v0; ce1 = ef * u1 + v1; ce2 = ef * u2 + v2;
            } else {
                ce0 = g_ce[eb + j0]; ce1 = g_ce[eb + j1]; ce2 = g_ce[eb + j2];
            }
            float bb0 = g_DB[sb2 + j0], bb1 = g_DB[sb2 + j1], bb2 = g_DB[sb2 + j2];
            float dh0 = g_DB[sb2 + D + j0], dh1 = g_DB[sb2 + D + j1], dh2 = g_DB[sb2 + D + j2];
            float en0 = ce0 + dh0 + eh0;
            float en1 = ce1 + dh1 + eh1;
            float en2 = ce2 + dh2 + eh2;
            float sg0 = 1.f / (1.f + __expf(-en0));
            float sg1 = 1.f / (1.f + __expf(-en1));
            float sg2 = 1.f / (1.f + __expf(-en2));
            num0 += bb0 * sg0; den0 += sg0;
            num1 += bb1 * sg1; den1 += sg1;
            num2 += bb2 * sg2; den2 += sg2;
            if (!LAST) {
                float sn = g_psn[e];
                float s0 = en0 * sn, s1 = en1 * sn, s2 = en2 * sn;
                g_enew[eb + j0] = s0;
                g_enew[eb + j1] = s1;
                if (m2) g_enew[eb + j2] = s2;
                lsE0 += s0; lqE0 += s0 * s0;
                lsE1 += s1; lqE1 += s1 * s1;
                lsE2 += s2; lqE2 += s2 * s2;
            }
        }
        float snn = snorm_n[n];
        float hv0 = (g_A[nb + j0] + num0 / (den0 + 1e-6f)) * snn;
        float hv1 = (g_A[nb + j1] + num1 / (den1 + 1e-6f)) * snn;
        float hv2 = (g_A[nb + j2] + num2 / (den2 + 1e-6f)) * snn;
        g_hraw[nb + j0] = hv0;
        g_hraw[nb + j1] = hv1;
        if (m2) g_hraw[nb + j2] = hv2;
        atomicAdd(&sStat[0][j0], hv0); atomicAdd(&sStat[1][j0], hv0 * hv0);
        atomicAdd(&sStat[0][j1], hv1); atomicAdd(&sStat[1][j1], hv1 * hv1);
        if (m2) { atomicAdd(&sStat[0][j2], hv2); atomicAdd(&sStat[1][j2], hv2 * hv2); }
        if (!LAST) {
            atomicAdd(&sStat[2][j0], lsE0); atomicAdd(&sStat[3][j0], lqE0);
            atomicAdd(&sStat[2][j1], lsE1); atomicAdd(&sStat[3][j1], lqE1);
            if (m2) { atomicAdd(&sStat[2][j2], lsE2); atomicAdd(&sStat[3][j2], lqE2); }
        }
    }
    __syncthreads();
    const int slot = blockIdx.x & 63;
    const int lim = LAST ? 2 * D : 4 * D;
    for (int i = threadIdx.x; i < lim; i += 256) {
        int st = i / D, j = i - st * D;
        atomicAdd(&g_statsf[st][slot][j], sStat[st][j]);
    }
}

// ---------------- finalize: reduce stat shards -> norms; next layer's u,v ----------------
__global__ void finalize_kernel(const float* __restrict__ WembE, const float* __restrict__ bembE,
                                const float* __restrict__ WCn, const float* __restrict__ bCn,
                                int Nn, int E_, int haveE) {
    int t = threadIdx.x;
    if (t < D) {
        float sh = 0.f, sq = 0.f;
        for (int s = 0; s < 64; s++) {
            sh += g_statsf[0][s][t]; g_statsf[0][s][t] = 0.f;
            sq += g_statsf[1][s][t]; g_statsf[1][s][t] = 0.f;
        }
        float mu = sh / Nn;
        float var = sq / Nn - mu * mu;
        g_norm[t] = mu;
        g_norm[D + t] = rsqrtf(fmaxf(var, 0.f) + 1e-5f);
        if (WCn) {
            float u = 0.f, v = 0.f;
            for (int k = 0; k < D; k++) {
                float w = WCn[k * D + t];
                u += WembE[k] * w;
                v += bembE[k] * w;
            }
            g_u[t] = u;
            g_v[t] = v + bCn[t];
        }
    } else if (t < 2 * D && haveE) {
        int j = t - D;
        float se = 0.f, sq = 0.f;
        for (int s = 0; s < 64; s++) {
            se += g_statsf[2][s][j]; g_statsf[2][s][j] = 0.f;
            sq += g_statsf[3][s][j]; g_statsf[3][s][j] = 0.f;
        }
        float mu = se / E_;
        float var = sq / E_ - mu * mu;
        g_norm[2 * D + j] = mu;
        g_norm[3 * D + j] = rsqrtf(fmaxf(var, 0.f) + 1e-5f);
    }
}

// ---------------- readout ----------------
__global__ void zero_readout_kernel() {
    int i = blockIdx.x * blockDim.x + threadIdx.x;
    if (i < GG * D) g_hg[i] = 0.f;
    if (i < GG) g_cnt[i] = 0.f;
}

__global__ void scatter_kernel(const int* __restrict__ gid,
                               const float* __restrict__ hgam, const float* __restrict__ hbet,
                               int Nn) {
    int j = threadIdx.x;
    float mu = g_norm[j], rs = g_norm[D + j], ga = hgam[j], bb = hbet[j];
    for (int row = blockIdx.x * 8 + threadIdx.y; row < Nn; row += gridDim.x * 8) {
        size_t idx = (size_t)row * D + j;
        float v = g_h[idx] + fmaxf((g_hraw[idx] - mu) * rs * ga + bb, 0.f);
        int g = gid[row];
        atomicAdd(&g_hg[g * D + j], v);
        if (j == 0) atomicAdd(&g_cnt[g], 1.f);
    }
}

__global__ void mlp_kernel(const float* __restrict__ W0, const float* __restrict__ b0,
                           const float* __restrict__ W1, const float* __restrict__ b1,
                           const float* __restrict__ W2, const float* __restrict__ b2,
                           float* __restrict__ out) {
    int g = threadIdx.x;
    if (g >= GG) return;
    float cnt = fmaxf(g_cnt[g], 1.f);
    float x[D];
#pragma unroll
    for (int k = 0; k < D; k++) x[k] = g_hg[g * D + k] / cnt;
    float y0[35];
#pragma unroll
    for (int o = 0; o < 35; o++) {
        float s = b0[o];
#pragma unroll
        for (int k = 0; k < D; k++) s += x[k] * W0[k * 35 + o];
        y0[o] = fmaxf(s, 0.f);
    }
    float y1[17];
#pragma unroll
    for (int o = 0; o < 17; o++) {
        float s = b1[o];
#pragma unroll
        for (int k = 0; k < 35; k++) s += y0[k] * W1[k * 17 + o];
        y1[o] = fmaxf(s, 0.f);
    }
#pragma unroll
    for (int o = 0; o < 10; o++) {
        float s = b2[o];
#pragma unroll
        for (int k = 0; k < 17; k++) s += y1[k] * W2[k * 10 + o];
        out[g * 10 + o] = s;
    }
}

// ---------------- host ----------------
extern "C" void kernel_launch(void* const* d_in, const int* in_sizes, int n_in,
                              void* d_out, int out_size) {
    const float* nodes   = (const float*)d_in[0];
    const float* ef      = (const float*)d_in[1];
    const float* snorm_n = (const float*)d_in[2];
    const float* snorm_e = (const float*)d_in[3];
    const int N = in_sizes[2];
    const int E_ = in_sizes[3];

    const int *src, *dst, *gid;
    const float *Wemb_h, *bemb_h, *Wemb_e, *bemb_e;
    const float *WA, *bA, *WB, *bB, *WC, *bC, *WDl, *bDl, *WEl, *bEl;
    const float *gh, *bh, *ge, *be, *W0, *b0, *W1, *b1, *W2, *b2;

    if (in_sizes[4] == E_) {
        src = (const int*)d_in[4]; dst = (const int*)d_in[5]; gid = (const int*)d_in[6];
        Wemb_h = (const float*)d_in[7];  bemb_h = (const float*)d_in[8];
        Wemb_e = (const float*)d_in[9];  bemb_e = (const float*)d_in[10];
        WA = (const float*)d_in[11]; bA = (const float*)d_in[12];
        WB = (const float*)d_in[13]; bB = (const float*)d_in[14];
        WC = (const float*)d_in[15]; bC = (const float*)d_in[16];
        WDl = (const float*)d_in[17]; bDl = (const float*)d_in[18];
        WEl = (const float*)d_in[19]; bEl = (const float*)d_in[20];
        gh = (const float*)d_in[21]; bh = (const float*)d_in[22];
        ge = (const float*)d_in[23]; be = (const float*)d_in[24];
        W0 = (const float*)d_in[25]; b0 = (const float*)d_in[26];
        W1 = (const float*)d_in[27]; b1 = (const float*)d_in[28];
        W2 = (const float*)d_in[29]; b2 = (const float*)d_in[30];
    } else {
        Wemb_h = (const float*)d_in[4];  bemb_h = (const float*)d_in[5];
        Wemb_e = (const float*)d_in[6];  bemb_e = (const float*)d_in[7];
        WA = (const float*)d_in[8];  bA = (const float*)d_in[9];
        WB = (const float*)d_in[10]; bB = (const float*)d_in[11];
        WC = (const float*)d_in[12]; bC = (const float*)d_in[13];
        WDl = (const float*)d_in[14]; bDl = (const float*)d_in[15];
        WEl = (const float*)d_in[16]; bEl = (const float*)d_in[17];
        gh = (const float*)d_in[18]; bh = (const float*)d_in[19];
        ge = (const float*)d_in[20]; be = (const float*)d_in[21];
        W0 = (const float*)d_in[22]; b0 = (const float*)d_in[23];
        W1 = (const float*)d_in[24]; b1 = (const float*)d_in[25];
        W2 = (const float*)d_in[26]; b2 = (const float*)d_in[27];
        src = (const int*)d_in[28]; dst = (const int*)d_in[29]; gid = (const int*)d_in[30];
    }
    float* out = (float*)d_out;

    float* ph;
    cudaGetSymbolAddress((void**)&ph, g_h);

    static cudaStream_t sA = nullptr, sB = nullptr;
    static cudaEvent_t evF = nullptr, evA = nullptr, evB = nullptr;
    if (sA == nullptr) {
        cudaStreamCreateWithFlags(&sA, cudaStreamNonBlocking);
        cudaStreamCreateWithFlags(&sB, cudaStreamNonBlocking);
        cudaEventCreateWithFlags(&evF, cudaEventDisableTiming);
        cudaEventCreateWithFlags(&evA, cudaEventDisableTiming);
        cudaEventCreateWithFlags(&evB, cudaEventDisableTiming);
    }
    cudaStream_t spine = 0;

    dim3 tbE(14, 16);
    dim3 tb2(7, 32);
    const int embBlocks = (N + 63) / 64;
    const int g4Blocks = (N + 127) / 128;
    const int egBlocks = (E_ + 127) / 128;
    const int aggBlocks = (N + 7) / 8;
    const int scanBlocks = (N + 1023) / 1024;
    const size_t smem146 = (size_t)(146 * D + 64 * 146) * sizeof(float);
    const size_t smemBig = (size_t)(D * D + 128 * D) * sizeof(float);
    cudaFuncSetAttribute(gemm70_kernel<146>, cudaFuncAttributeMaxDynamicSharedMemorySize, (int)smem146);
    cudaFuncSetAttribute(gemm4_kernel, cudaFuncAttributeMaxDynamicSharedMemorySize, (int)smemBig);
    cudaFuncSetAttribute(edgegemm_kernel<1, 1>, cudaFuncAttributeMaxDynamicSharedMemorySize, (int)smemBig);
    cudaFuncSetAttribute(edgegemm_kernel<0, 1>, cudaFuncAttributeMaxDynamicSharedMemorySize, (int)smemBig);
    cudaFuncSetAttribute(edgegemm_kernel<0, 0>, cudaFuncAttributeMaxDynamicSharedMemorySize, (int)smemBig);

    // ---- prologue: {emb -> gemm4_0} on sA  ||  {hist -> scan x3 -> scatter -> uv} on sB ----
    cudaEventRecord(evF, spine);
    cudaStreamWaitEvent(sA, evF, 0);
    cudaStreamWaitEvent(sB, evF, 0);

    gemm70_kernel<146><<<embBlocks, tbE, smem146, sA>>>(nodes, Wemb_h, bemb_h, ph, N);
    gemm4_kernel<<<g4Blocks, tb2, smemBig, sA>>>(WA, bA, WB, bB, WDl, bDl, WEl, bEl,
                                                 nullptr, nullptr, 0, N);
    cudaEventRecord(evA, sA);

    hist_kernel<<<(E_ + 255) / 256, 256, 0, sB>>>(dst, E_);
    scan1_kernel<<<scanBlocks, 1024, 0, sB>>>(N);
    scan2_kernel<<<1, 32, 0, sB>>>(scanBlocks);
    scan3_kernel<<<scanBlocks, 1024, 0, sB>>>(N, E_);
    scatter_sort_kernel<<<(E_ + 255) / 256, 256, 0, sB>>>(src, dst, ef, snorm_e, E_);
    uv_kernel<<<1, D, 0, sB>>>(Wemb_e, bemb_e, WC, bC);
    cudaEventRecord(evB, sB);

    cudaStreamWaitEvent(spine, evA, 0);
    cudaStreamWaitEvent(spine, evB, 0);

    agg_kernel<1, 0><<<aggBlocks, 256, 0, spine>>>(snorm_n, N);
    finalize_kernel<<<1, 2 * D, 0, spine>>>(Wemb_e, bemb_e, WC + 1 * D * D, bC + 1 * D,
                                            N, E_, 1);

    // ---- layers 1..3: gemm4 || edgegemm, then agg -> finalize ----
    for (int l = 1; l < 4; l++) {
        const float* wA = WA + l * D * D; const float* biA = bA + l * D;
        const float* wB = WB + l * D * D; const float* biB = bB + l * D;
        const float* wC = WC + l * D * D;
        const float* wD = WDl + l * D * D; const float* biD = bDl + l * D;
        const float* wE = WEl + l * D * D; const float* biE = bEl + l * D;

        cudaEventRecord(evF, spine);
        cudaStreamWaitEvent(sA, evF, 0);
        cudaStreamWaitEvent(sB, evF, 0);

        gemm4_kernel<<<g4Blocks, tb2, smemBig, sA>>>(wA, biA, wB, biB, wD, biD, wE, biE,
                                                     gh + (l - 1) * D, bh + (l - 1) * D, 1, N);
        cudaEventRecord(evA, sA);

        const float* eg = ge + (l - 1) * D;
        const float* eb = be + (l - 1) * D;
        if (l == 1)
            edgegemm_kernel<1, 1><<<egBlocks, tb2, smemBig, sB>>>(wC, eg, eb, E_);
        else if (l == 2)
            edgegemm_kernel<0, 1><<<egBlocks, tb2, smemBig, sB>>>(wC, eg, eb, E_);
        else
            edgegemm_kernel<0, 0><<<egBlocks, tb2, smemBig, sB>>>(wC, eg, eb, E_);
        cudaEventRecord(evB, sB);

        cudaStreamWaitEvent(spine, evA, 0);
        cudaStreamWaitEvent(spine, evB, 0);

        if (l == 3) {
            agg_kernel<0, 1><<<aggBlocks, 256, 0, spine>>>(snorm_n, N);
            finalize_kernel<<<1, 2 * D, 0, spine>>>(Wemb_e, bemb_e, nullptr, nullptr, N, E_, 0);
        } else {
            agg_kernel<0, 0><<<aggBlocks, 256, 0, spine>>>(snorm_n, N);
            finalize_kernel<<<1, 2 * D, 0, spine>>>(Wemb_e, bemb_e, WC + (l + 1) * D * D,
                                                    bC + (l + 1) * D, N, E_, 1);
        }
    }

    // ---- readout ----
    zero_readout_kernel<<<(GG * D + 255) / 256, 256, 0, spine>>>();
    scatter_kernel<<<(N + 7) / 8, dim3(D, 8), 0, spine>>>(gid, gh + 3 * D, bh + 3 * D, N);
    mlp_kernel<<<1, GG, 0, spine>>>(W0, b0, W1, b1, W2, b2, out);
}